// round 5
// baseline (speedup 1.0000x reference)
#include <cuda_runtime.h>
#include <cstdint>

// ---------------- problem constants ----------------
#define MTOT 65536      // B*T tokens
#define EF   256
#define HF   256
#define NBLK 6
#define TLEN 2048
#define BB   32
#define NC   32
#define TC   64

#define ASTR 132        // smem row stride (floats)
#define BSTRG 68        // GLU B tile stride

typedef unsigned long long u64t;

// ---------------- scratch ----------------
static __device__ float g_y[(size_t)MTOT * EF];
static __device__ float g_x[(size_t)MTOT * EF];
static __device__ float g_bure[(size_t)MTOT * HF];
static __device__ float g_buim[(size_t)MTOT * HF];
static __device__ float g_hre[(size_t)MTOT * HF];
static __device__ float g_him[(size_t)MTOT * HF];
static __device__ float g_u[(size_t)MTOT * EF];
static __device__ float g_g[(size_t)MTOT * 512];
static __device__ float g_part[256 * 512];
static __device__ float g_bna[EF], g_bnc[EF];
static __device__ float g_lr[HF], g_li[HF], g_gam[HF], g_L64r[HF], g_L64i[HF];
static __device__ float g_car_re[BB * NC * HF], g_car_im[BB * NC * HF];
static __device__ float g_pre_re[BB * NC * HF], g_pre_im[BB * NC * HF];
static __device__ float g_poolpart[BB * 8 * EF];
static __device__ float g_pool[BB * EF];

// ---------------- f32x2 helpers ----------------
__device__ __forceinline__ void fma2(u64t& d, u64t a, u64t b) {
    asm("fma.rn.f32x2 %0, %1, %2, %3;" : "=l"(d) : "l"(a), "l"(b), "l"(d));
}
__device__ __forceinline__ float2 up2(u64t v) {
    float2 f;
    asm("mov.b64 {%0, %1}, %2;" : "=f"(f.x), "=f"(f.y) : "l"(v));
    return f;
}
__device__ __forceinline__ u64t pk(float f) {
    u64t o;
    asm("mov.b64 %0, {%1, %1};" : "=l"(o) : "f"(f));
    return o;
}

// ================= BN statistics =================
__global__ void __launch_bounds__(256) bn_stage1(int xsel) {
    const float* x = xsel ? g_x : g_y;
    int blk = blockIdx.x;
    int e = threadIdx.x;
    const float* p = x + (size_t)blk * 256 * EF + e;
    float s = 0.f, s2 = 0.f;
    for (int r = 0; r < 256; r++) {
        float v = p[(size_t)r * EF];
        s += v;
        s2 += v * v;
    }
    g_part[blk * 512 + e] = s;
    g_part[blk * 512 + 256 + e] = s2;
}
__global__ void __launch_bounds__(256) bn_stage2(const float* __restrict__ scale,
                                                 const float* __restrict__ bias) {
    int e = threadIdx.x;
    float s = 0.f, s2 = 0.f;
    for (int p = 0; p < 256; p++) {
        s += g_part[p * 512 + e];
        s2 += g_part[p * 512 + 256 + e];
    }
    const float inv = 1.0f / 65536.0f;
    float mu = s * inv;
    float var = fmaxf(s2 * inv - mu * mu, 0.0f);
    float a = rsqrtf(var + 1e-5f) * scale[e];
    g_bna[e] = a;
    g_bnc[e] = bias[e] - mu * a;
}

// ================= lambda / gamma =================
__global__ void lam_kernel(const float* __restrict__ nul, const float* __restrict__ thl) {
    int h = threadIdx.x;
    float nu = expf(nul[h]);
    float th = expf(thl[h]);
    float r = expf(-nu);
    float sn, cs;
    sincosf(th, &sn, &cs);
    float lr = r * cs, li = r * sn;
    g_lr[h] = lr;
    g_li[h] = li;
    g_gam[h] = sqrtf(fmaxf(1.0f - r * r, 1e-12f));
    float ar = lr, ai = li;
#pragma unroll
    for (int s = 0; s < 6; s++) {
        float nr = ar * ar - ai * ai;
        float ni = 2.0f * ar * ai;
        ar = nr;
        ai = ni;
    }
    g_L64r[h] = ar;
    g_L64i[h] = ai;
}

// ================= GEMM: Bu = BN(x) @ B^T * gamma (TN, dup-B, double-buffered) =================
__global__ void __launch_bounds__(256) gemm_bu(int xsel, const float* __restrict__ W, int osel) {
    __shared__ __align__(16) float As[2][16 * ASTR];
    __shared__ __align__(16) float Bs[2][16 * ASTR];   // duplicated {b,b} pairs
    const float* A = xsel ? g_x : g_y;
    float* out = osel ? g_buim : g_bure;
    const int tid = threadIdx.x;
    const int m0 = blockIdx.x * 128;
    const int n0 = blockIdx.y * 64;
    const int tx = tid & 15;
    const int ty = tid >> 4;
    const int lr = tid >> 2;
    const int lk = (tid & 3) * 4;

    float4 pa0, pa1, pw;
    auto fetch = [&](int k0) {
        pa0 = *(const float4*)(A + (size_t)(m0 + lr) * 256 + k0 + lk);
        pa1 = *(const float4*)(A + (size_t)(m0 + lr + 64) * 256 + k0 + lk);
        pw = *(const float4*)(W + (size_t)(n0 + lr) * 256 + k0 + lk);
        float4 ba = *(const float4*)(g_bna + k0 + lk);
        float4 bc = *(const float4*)(g_bnc + k0 + lk);
        pa0.x = fmaf(ba.x, pa0.x, bc.x); pa0.y = fmaf(ba.y, pa0.y, bc.y);
        pa0.z = fmaf(ba.z, pa0.z, bc.z); pa0.w = fmaf(ba.w, pa0.w, bc.w);
        pa1.x = fmaf(ba.x, pa1.x, bc.x); pa1.y = fmaf(ba.y, pa1.y, bc.y);
        pa1.z = fmaf(ba.z, pa1.z, bc.z); pa1.w = fmaf(ba.w, pa1.w, bc.w);
    };
    auto store = [&](int buf) {
        float* a = As[buf];
        float* b = Bs[buf];
        a[(lk + 0) * ASTR + lr] = pa0.x; a[(lk + 1) * ASTR + lr] = pa0.y;
        a[(lk + 2) * ASTR + lr] = pa0.z; a[(lk + 3) * ASTR + lr] = pa0.w;
        a[(lk + 0) * ASTR + lr + 64] = pa1.x; a[(lk + 1) * ASTR + lr + 64] = pa1.y;
        a[(lk + 2) * ASTR + lr + 64] = pa1.z; a[(lk + 3) * ASTR + lr + 64] = pa1.w;
        *(float2*)&b[(lk + 0) * ASTR + 2 * lr] = make_float2(pw.x, pw.x);
        *(float2*)&b[(lk + 1) * ASTR + 2 * lr] = make_float2(pw.y, pw.y);
        *(float2*)&b[(lk + 2) * ASTR + 2 * lr] = make_float2(pw.z, pw.z);
        *(float2*)&b[(lk + 3) * ASTR + 2 * lr] = make_float2(pw.w, pw.w);
    };

    u64t acc[4][4];
#pragma unroll
    for (int i = 0; i < 4; i++)
#pragma unroll
        for (int j = 0; j < 4; j++) acc[i][j] = 0ull;

    fetch(0);
    store(0);
    __syncthreads();
    for (int c = 0; c < 16; c++) {
        if (c + 1 < 16) fetch((c + 1) * 16);
        const float* as = As[c & 1];
        const float* bs = Bs[c & 1];
#pragma unroll
        for (int kk = 0; kk < 16; kk++) {
            ulonglong2 a0 = *(const ulonglong2*)&as[kk * ASTR + ty * 8];
            ulonglong2 a1 = *(const ulonglong2*)&as[kk * ASTR + ty * 8 + 4];
            ulonglong2 b0 = *(const ulonglong2*)&bs[kk * ASTR + tx * 8];
            ulonglong2 b1 = *(const ulonglong2*)&bs[kk * ASTR + tx * 8 + 4];
            u64t av[4] = {a0.x, a0.y, a1.x, a1.y};
            u64t bv[4] = {b0.x, b0.y, b1.x, b1.y};
#pragma unroll
            for (int mp = 0; mp < 4; mp++)
#pragma unroll
                for (int n = 0; n < 4; n++) fma2(acc[mp][n], av[mp], bv[n]);
        }
        if (c + 1 < 16) store((c + 1) & 1);
        __syncthreads();
    }

    float4 gm = *(const float4*)(g_gam + n0 + tx * 4);
#pragma unroll
    for (int mp = 0; mp < 4; mp++) {
        float2 p0 = up2(acc[mp][0]), p1 = up2(acc[mp][1]);
        float2 p2 = up2(acc[mp][2]), p3 = up2(acc[mp][3]);
        float4 olo = make_float4(p0.x * gm.x, p1.x * gm.y, p2.x * gm.z, p3.x * gm.w);
        float4 ohi = make_float4(p0.y * gm.x, p1.y * gm.y, p2.y * gm.z, p3.y * gm.w);
        size_t row = (size_t)(m0 + ty * 8 + 2 * mp);
        *(float4*)(out + row * 256 + n0 + tx * 4) = olo;
        *(float4*)(out + (row + 1) * 256 + n0 + tx * 4) = ohi;
    }
}

// ================= GEMM: u = Re(hs@Cc) + D*BN(x) (dual TN, dup-B, single-buffered) ========
__global__ void __launch_bounds__(256) gemm_cproj(const float* __restrict__ Wr,
                                                  const float* __restrict__ Wi,
                                                  const float* __restrict__ Dv, int xsel) {
    __shared__ __align__(16) float Asr[16 * ASTR];
    __shared__ __align__(16) float Asi[16 * ASTR];
    __shared__ __align__(16) float Bsr[16 * ASTR];
    __shared__ __align__(16) float Bsi[16 * ASTR];
    const float* Xin = xsel ? g_x : g_y;
    const int tid = threadIdx.x;
    const int m0 = blockIdx.x * 128;
    const int n0 = blockIdx.y * 64;
    const int tx = tid & 15;
    const int ty = tid >> 4;
    const int lr = tid >> 2;
    const int lk = (tid & 3) * 4;

    float4 pr0, pr1, pi0, pi1, pwr, pwi;
    auto fetch = [&](int k0) {
        pr0 = *(const float4*)(g_hre + (size_t)(m0 + lr) * 256 + k0 + lk);
        pr1 = *(const float4*)(g_hre + (size_t)(m0 + lr + 64) * 256 + k0 + lk);
        pi0 = *(const float4*)(g_him + (size_t)(m0 + lr) * 256 + k0 + lk);
        pi1 = *(const float4*)(g_him + (size_t)(m0 + lr + 64) * 256 + k0 + lk);
        pwr = *(const float4*)(Wr + (size_t)(n0 + lr) * 256 + k0 + lk);
        pwi = *(const float4*)(Wi + (size_t)(n0 + lr) * 256 + k0 + lk);
    };
    auto store = [&]() {
        Asr[(lk + 0) * ASTR + lr] = pr0.x; Asr[(lk + 1) * ASTR + lr] = pr0.y;
        Asr[(lk + 2) * ASTR + lr] = pr0.z; Asr[(lk + 3) * ASTR + lr] = pr0.w;
        Asr[(lk + 0) * ASTR + lr + 64] = pr1.x; Asr[(lk + 1) * ASTR + lr + 64] = pr1.y;
        Asr[(lk + 2) * ASTR + lr + 64] = pr1.z; Asr[(lk + 3) * ASTR + lr + 64] = pr1.w;
        Asi[(lk + 0) * ASTR + lr] = pi0.x; Asi[(lk + 1) * ASTR + lr] = pi0.y;
        Asi[(lk + 2) * ASTR + lr] = pi0.z; Asi[(lk + 3) * ASTR + lr] = pi0.w;
        Asi[(lk + 0) * ASTR + lr + 64] = pi1.x; Asi[(lk + 1) * ASTR + lr + 64] = pi1.y;
        Asi[(lk + 2) * ASTR + lr + 64] = pi1.z; Asi[(lk + 3) * ASTR + lr + 64] = pi1.w;
        *(float2*)&Bsr[(lk + 0) * ASTR + 2 * lr] = make_float2(pwr.x, pwr.x);
        *(float2*)&Bsr[(lk + 1) * ASTR + 2 * lr] = make_float2(pwr.y, pwr.y);
        *(float2*)&Bsr[(lk + 2) * ASTR + 2 * lr] = make_float2(pwr.z, pwr.z);
        *(float2*)&Bsr[(lk + 3) * ASTR + 2 * lr] = make_float2(pwr.w, pwr.w);
        *(float2*)&Bsi[(lk + 0) * ASTR + 2 * lr] = make_float2(-pwi.x, -pwi.x);
        *(float2*)&Bsi[(lk + 1) * ASTR + 2 * lr] = make_float2(-pwi.y, -pwi.y);
        *(float2*)&Bsi[(lk + 2) * ASTR + 2 * lr] = make_float2(-pwi.z, -pwi.z);
        *(float2*)&Bsi[(lk + 3) * ASTR + 2 * lr] = make_float2(-pwi.w, -pwi.w);
    };

    u64t acc[4][4];
#pragma unroll
    for (int i = 0; i < 4; i++)
#pragma unroll
        for (int j = 0; j < 4; j++) acc[i][j] = 0ull;

    fetch(0);
    for (int c = 0; c < 16; c++) {
        __syncthreads();
        store();
        __syncthreads();
        if (c + 1 < 16) fetch((c + 1) * 16);
#pragma unroll
        for (int kk = 0; kk < 16; kk++) {
            ulonglong2 r0 = *(const ulonglong2*)&Asr[kk * ASTR + ty * 8];
            ulonglong2 r1 = *(const ulonglong2*)&Asr[kk * ASTR + ty * 8 + 4];
            ulonglong2 i0 = *(const ulonglong2*)&Asi[kk * ASTR + ty * 8];
            ulonglong2 i1 = *(const ulonglong2*)&Asi[kk * ASTR + ty * 8 + 4];
            ulonglong2 br0 = *(const ulonglong2*)&Bsr[kk * ASTR + tx * 8];
            ulonglong2 br1 = *(const ulonglong2*)&Bsr[kk * ASTR + tx * 8 + 4];
            ulonglong2 bi0 = *(const ulonglong2*)&Bsi[kk * ASTR + tx * 8];
            ulonglong2 bi1 = *(const ulonglong2*)&Bsi[kk * ASTR + tx * 8 + 4];
            u64t ar[4] = {r0.x, r0.y, r1.x, r1.y};
            u64t ai[4] = {i0.x, i0.y, i1.x, i1.y};
            u64t br[4] = {br0.x, br0.y, br1.x, br1.y};
            u64t bi[4] = {bi0.x, bi0.y, bi1.x, bi1.y};
#pragma unroll
            for (int mp = 0; mp < 4; mp++)
#pragma unroll
                for (int n = 0; n < 4; n++) {
                    fma2(acc[mp][n], ar[mp], br[n]);
                    fma2(acc[mp][n], ai[mp], bi[n]);
                }
        }
    }

    float4 dq = *(const float4*)(Dv + n0 + tx * 4);
    float4 ba = *(const float4*)(g_bna + n0 + tx * 4);
    float4 bc = *(const float4*)(g_bnc + n0 + tx * 4);
#pragma unroll
    for (int mp = 0; mp < 4; mp++) {
        float2 p0 = up2(acc[mp][0]), p1 = up2(acc[mp][1]);
        float2 p2 = up2(acc[mp][2]), p3 = up2(acc[mp][3]);
#pragma unroll
        for (int half = 0; half < 2; half++) {
            size_t row = (size_t)(m0 + ty * 8 + 2 * mp + half);
            float4 xv = *(const float4*)(Xin + row * 256 + n0 + tx * 4);
            float4 o;
            float v0 = half ? p0.y : p0.x, v1 = half ? p1.y : p1.x;
            float v2 = half ? p2.y : p2.x, v3 = half ? p3.y : p3.x;
            o.x = v0 + dq.x * fmaf(ba.x, xv.x, bc.x);
            o.y = v1 + dq.y * fmaf(ba.y, xv.y, bc.y);
            o.z = v2 + dq.z * fmaf(ba.z, xv.z, bc.z);
            o.w = v3 + dq.w * fmaf(ba.w, xv.w, bc.w);
            *(float4*)(g_u + row * 256 + n0 + tx * 4) = o;
        }
    }
}

// ================= GEMM: g = GLU(u @ W1 + b1) (NN dual-B, double-buffered) ============
__global__ void __launch_bounds__(256) gemm_glu(const float* __restrict__ W1,
                                                const float* __restrict__ b1) {
    __shared__ __align__(16) float As[2][16 * ASTR];
    __shared__ __align__(16) float Ba[2][16 * BSTRG];
    __shared__ __align__(16) float Bb[2][16 * BSTRG];
    const int tid = threadIdx.x;
    const int m0 = blockIdx.x * 128;
    const int n0 = blockIdx.y * 64;
    const int tx = tid & 15;
    const int ty = tid >> 4;
    const int lr = tid >> 2;
    const int lk = (tid & 3) * 4;
    const int bk = tid >> 4;
    const int bn = (tid & 15) * 4;

    float4 pa0, pa1, pwa, pwb;
    auto fetch = [&](int k0) {
        pa0 = *(const float4*)(g_u + (size_t)(m0 + lr) * 256 + k0 + lk);
        pa1 = *(const float4*)(g_u + (size_t)(m0 + lr + 64) * 256 + k0 + lk);
        pwa = *(const float4*)(W1 + (size_t)(k0 + bk) * 1024 + n0 + bn);
        pwb = *(const float4*)(W1 + (size_t)(k0 + bk) * 1024 + 512 + n0 + bn);
    };
    auto store = [&](int buf) {
        float* a = As[buf];
        a[(lk + 0) * ASTR + lr] = pa0.x; a[(lk + 1) * ASTR + lr] = pa0.y;
        a[(lk + 2) * ASTR + lr] = pa0.z; a[(lk + 3) * ASTR + lr] = pa0.w;
        a[(lk + 0) * ASTR + lr + 64] = pa1.x; a[(lk + 1) * ASTR + lr + 64] = pa1.y;
        a[(lk + 2) * ASTR + lr + 64] = pa1.z; a[(lk + 3) * ASTR + lr + 64] = pa1.w;
        *(float4*)&Ba[buf][bk * BSTRG + bn] = pwa;
        *(float4*)&Bb[buf][bk * BSTRG + bn] = pwb;
    };

    u64t acca[4][4], accb[4][4];
#pragma unroll
    for (int i = 0; i < 4; i++)
#pragma unroll
        for (int j = 0; j < 4; j++) { acca[i][j] = 0ull; accb[i][j] = 0ull; }

    fetch(0);
    store(0);
    __syncthreads();
    for (int c = 0; c < 16; c++) {
        if (c + 1 < 16) fetch((c + 1) * 16);
        const float* as = As[c & 1];
        const float* bas = Ba[c & 1];
        const float* bbs = Bb[c & 1];
#pragma unroll
        for (int kk = 0; kk < 16; kk++) {
            ulonglong2 a0 = *(const ulonglong2*)&as[kk * ASTR + ty * 8];
            ulonglong2 a1 = *(const ulonglong2*)&as[kk * ASTR + ty * 8 + 4];
            float4 ba4 = *(const float4*)&bas[kk * BSTRG + tx * 4];
            float4 bb4 = *(const float4*)&bbs[kk * BSTRG + tx * 4];
            u64t av[4] = {a0.x, a0.y, a1.x, a1.y};
            u64t pba[4] = {pk(ba4.x), pk(ba4.y), pk(ba4.z), pk(ba4.w)};
            u64t pbb[4] = {pk(bb4.x), pk(bb4.y), pk(bb4.z), pk(bb4.w)};
#pragma unroll
            for (int mp = 0; mp < 4; mp++)
#pragma unroll
                for (int n = 0; n < 4; n++) {
                    fma2(acca[mp][n], av[mp], pba[n]);
                    fma2(accb[mp][n], av[mp], pbb[n]);
                }
        }
        if (c + 1 < 16) store((c + 1) & 1);
        __syncthreads();
    }

    float4 b1a = *(const float4*)(b1 + n0 + tx * 4);
    float4 b1b = *(const float4*)(b1 + 512 + n0 + tx * 4);
#pragma unroll
    for (int mp = 0; mp < 4; mp++) {
        float2 a0 = up2(acca[mp][0]), a1 = up2(acca[mp][1]);
        float2 a2 = up2(acca[mp][2]), a3 = up2(acca[mp][3]);
        float2 q0 = up2(accb[mp][0]), q1 = up2(accb[mp][1]);
        float2 q2 = up2(accb[mp][2]), q3 = up2(accb[mp][3]);
#pragma unroll
        for (int half = 0; half < 2; half++) {
            size_t row = (size_t)(m0 + ty * 8 + 2 * mp + half);
            float za0 = (half ? a0.y : a0.x) + b1a.x;
            float za1 = (half ? a1.y : a1.x) + b1a.y;
            float za2 = (half ? a2.y : a2.x) + b1a.z;
            float za3 = (half ? a3.y : a3.x) + b1a.w;
            float zb0 = (half ? q0.y : q0.x) + b1b.x;
            float zb1 = (half ? q1.y : q1.x) + b1b.y;
            float zb2 = (half ? q2.y : q2.x) + b1b.z;
            float zb3 = (half ? q3.y : q3.x) + b1b.w;
            float4 o;
            o.x = za0 / (1.0f + expf(-zb0));
            o.y = za1 / (1.0f + expf(-zb1));
            o.z = za2 / (1.0f + expf(-zb2));
            o.w = za3 / (1.0f + expf(-zb3));
            *(float4*)(g_g + row * 512 + n0 + tx * 4) = o;
        }
    }
}

// ================= GEMM NN (encoder ROLE=0, MLP2+residual ROLE=1), dup-B, dbuf ==========
template <int ROLE>
__global__ void __launch_bounds__(256) gemm_nn(const float* __restrict__ Aext, int K,
                                               const float* __restrict__ B,
                                               const float* __restrict__ bias) {
    __shared__ __align__(16) float As[2][16 * ASTR];
    __shared__ __align__(16) float Bs[2][16 * ASTR];
    const float* A = (ROLE == 0) ? Aext : g_g;
    float* out = (ROLE == 0) ? g_y : g_x;
    const int tid = threadIdx.x;
    const int m0 = blockIdx.x * 128;
    const int n0 = blockIdx.y * 64;
    const int tx = tid & 15;
    const int ty = tid >> 4;
    const int lr = tid >> 2;
    const int lk = (tid & 3) * 4;
    const int bk = tid >> 4;
    const int bn = (tid & 15) * 4;
    const int nch = K / 16;

    float4 pa0, pa1, pw;
    auto fetch = [&](int k0) {
        pa0 = *(const float4*)(A + (size_t)(m0 + lr) * K + k0 + lk);
        pa1 = *(const float4*)(A + (size_t)(m0 + lr + 64) * K + k0 + lk);
        pw = *(const float4*)(B + (size_t)(k0 + bk) * 256 + n0 + bn);
    };
    auto store = [&](int buf) {
        float* a = As[buf];
        float* b = Bs[buf];
        a[(lk + 0) * ASTR + lr] = pa0.x; a[(lk + 1) * ASTR + lr] = pa0.y;
        a[(lk + 2) * ASTR + lr] = pa0.z; a[(lk + 3) * ASTR + lr] = pa0.w;
        a[(lk + 0) * ASTR + lr + 64] = pa1.x; a[(lk + 1) * ASTR + lr + 64] = pa1.y;
        a[(lk + 2) * ASTR + lr + 64] = pa1.z; a[(lk + 3) * ASTR + lr + 64] = pa1.w;
        *(float2*)&b[bk * ASTR + 2 * (bn + 0)] = make_float2(pw.x, pw.x);
        *(float2*)&b[bk * ASTR + 2 * (bn + 1)] = make_float2(pw.y, pw.y);
        *(float2*)&b[bk * ASTR + 2 * (bn + 2)] = make_float2(pw.z, pw.z);
        *(float2*)&b[bk * ASTR + 2 * (bn + 3)] = make_float2(pw.w, pw.w);
    };

    u64t acc[4][4];
#pragma unroll
    for (int i = 0; i < 4; i++)
#pragma unroll
        for (int j = 0; j < 4; j++) acc[i][j] = 0ull;

    fetch(0);
    store(0);
    __syncthreads();
    for (int c = 0; c < nch; c++) {
        if (c + 1 < nch) fetch((c + 1) * 16);
        const float* as = As[c & 1];
        const float* bs = Bs[c & 1];
#pragma unroll
        for (int kk = 0; kk < 16; kk++) {
            ulonglong2 a0 = *(const ulonglong2*)&as[kk * ASTR + ty * 8];
            ulonglong2 a1 = *(const ulonglong2*)&as[kk * ASTR + ty * 8 + 4];
            ulonglong2 b0 = *(const ulonglong2*)&bs[kk * ASTR + tx * 8];
            ulonglong2 b1 = *(const ulonglong2*)&bs[kk * ASTR + tx * 8 + 4];
            u64t av[4] = {a0.x, a0.y, a1.x, a1.y};
            u64t bv[4] = {b0.x, b0.y, b1.x, b1.y};
#pragma unroll
            for (int mp = 0; mp < 4; mp++)
#pragma unroll
                for (int n = 0; n < 4; n++) fma2(acc[mp][n], av[mp], bv[n]);
        }
        if (c + 1 < nch) store((c + 1) & 1);
        __syncthreads();
    }

    float4 bq = *(const float4*)(bias + n0 + tx * 4);
#pragma unroll
    for (int mp = 0; mp < 4; mp++) {
        float2 p0 = up2(acc[mp][0]), p1 = up2(acc[mp][1]);
        float2 p2 = up2(acc[mp][2]), p3 = up2(acc[mp][3]);
#pragma unroll
        for (int half = 0; half < 2; half++) {
            size_t row = (size_t)(m0 + ty * 8 + 2 * mp + half);
            float4 o;
            o.x = (half ? p0.y : p0.x) + bq.x;
            o.y = (half ? p1.y : p1.x) + bq.y;
            o.z = (half ? p2.y : p2.x) + bq.z;
            o.w = (half ? p3.y : p3.x) + bq.w;
            if (ROLE == 1) {
                float4 yv = *(const float4*)(g_y + row * 256 + n0 + tx * 4);
                o.x += yv.x; o.y += yv.y; o.z += yv.z; o.w += yv.w;
            }
            *(float4*)(out + row * 256 + n0 + tx * 4) = o;
        }
    }
}

// ================= chunked scan =================
__global__ void __launch_bounds__(256) scan_carry() {
    int h = threadIdx.x;
    int c = blockIdx.x & 31;
    int b = blockIdx.x >> 5;
    float lr = g_lr[h], li = g_li[h];
    float hr = 0.f, hi = 0.f;
    size_t base = ((size_t)b * TLEN + c * TC) * HF + h;
#pragma unroll 4
    for (int t = 0; t < TC; t++) {
        float ur = g_bure[base + (size_t)t * HF];
        float ui = g_buim[base + (size_t)t * HF];
        float nr = fmaf(lr, hr, fmaf(-li, hi, ur));
        float ni = fmaf(lr, hi, fmaf(li, hr, ui));
        hr = nr;
        hi = ni;
    }
    int ci = (b * NC + c) * HF + h;
    g_car_re[ci] = hr;
    g_car_im[ci] = hi;
}
__global__ void __launch_bounds__(256) scan_prefix() {
    int h = threadIdx.x;
    int b = blockIdx.x;
    float Lr = g_L64r[h], Li = g_L64i[h];
    float Hr = 0.f, Hi = 0.f;
    for (int c = 0; c < NC; c++) {
        int ci = (b * NC + c) * HF + h;
        g_pre_re[ci] = Hr;
        g_pre_im[ci] = Hi;
        float cr = g_car_re[ci], cim = g_car_im[ci];
        float nr = fmaf(Lr, Hr, fmaf(-Li, Hi, cr));
        float ni = fmaf(Lr, Hi, fmaf(Li, Hr, cim));
        Hr = nr;
        Hi = ni;
    }
}
__global__ void __launch_bounds__(256) scan_final() {
    int h = threadIdx.x;
    int c = blockIdx.x & 31;
    int b = blockIdx.x >> 5;
    float lr = g_lr[h], li = g_li[h];
    int ci = (b * NC + c) * HF + h;
    float hr = g_pre_re[ci], hi = g_pre_im[ci];
    size_t base = ((size_t)b * TLEN + c * TC) * HF + h;
#pragma unroll 4
    for (int t = 0; t < TC; t++) {
        size_t idx = base + (size_t)t * HF;
        float ur = g_bure[idx];
        float ui = g_buim[idx];
        float nr = fmaf(lr, hr, fmaf(-li, hi, ur));
        float ni = fmaf(lr, hi, fmaf(li, hr, ui));
        hr = nr;
        hi = ni;
        g_hre[idx] = hr;
        g_him[idx] = hi;
    }
}

// ================= pool + head =================
__global__ void __launch_bounds__(256) pool1() {
    int b = blockIdx.x >> 3;
    int c = blockIdx.x & 7;
    int e = threadIdx.x;
    const float* p = g_x + ((size_t)b * TLEN + c * 256) * EF + e;
    float s = 0.f;
#pragma unroll 8
    for (int t = 0; t < 256; t++) s += p[(size_t)t * EF];
    g_poolpart[(b * 8 + c) * EF + e] = s;
}
__global__ void __launch_bounds__(256) pool2() {
    int b = blockIdx.x;
    int e = threadIdx.x;
    float s = 0.f;
    for (int c = 0; c < 8; c++) s += g_poolpart[(b * 8 + c) * EF + e];
    g_pool[b * EF + e] = s * (1.0f / (float)TLEN);
}
__global__ void head(const float* __restrict__ Wout, const float* __restrict__ bout,
                     float* __restrict__ out) {
    int tid = threadIdx.x;
    if (tid >= 320) return;
    int b = tid / 10;
    int o = tid % 10;
    float s = bout[o];
    const float* p = g_pool + b * EF;
    for (int e = 0; e < 256; e++) s = fmaf(p[e], Wout[e * 10 + o], s);
    out[b * 10 + o] = s;
}

// ================= host orchestration =================
extern "C" void kernel_launch(void* const* d_in, const int* in_sizes, int n_in,
                              void* d_out, int out_size) {
    const float* x    = (const float*)d_in[0];
    const float* Wenc = (const float*)d_in[1];
    const float* benc = (const float*)d_in[2];
    const float* nul  = (const float*)d_in[3];
    const float* thl  = (const float*)d_in[4];
    const float* Bre  = (const float*)d_in[5];
    const float* Bim  = (const float*)d_in[6];
    const float* Cre  = (const float*)d_in[7];
    const float* Cim  = (const float*)d_in[8];
    const float* Dd   = (const float*)d_in[9];
    const float* W1   = (const float*)d_in[10];
    const float* b1   = (const float*)d_in[11];
    const float* W2   = (const float*)d_in[12];
    const float* b2   = (const float*)d_in[13];
    const float* bns  = (const float*)d_in[14];
    const float* bnb  = (const float*)d_in[15];
    const float* Wout = (const float*)d_in[16];
    const float* bout = (const float*)d_in[17];

    dim3 g4(512, 4), g8(512, 8);

    // encoder: y = x @ W_enc + b_enc
    gemm_nn<0><<<g4, 256>>>(x, 64, Wenc, benc);

    int xsel = 0;
    for (int i = 0; i < NBLK; i++) {
        bn_stage1<<<256, 256>>>(xsel);
        bn_stage2<<<1, 256>>>(bns + i * 256, bnb + i * 256);
        lam_kernel<<<1, 256>>>(nul + i * 256, thl + i * 256);
        gemm_bu<<<g4, 256>>>(xsel, Bre + (size_t)i * 65536, 0);
        gemm_bu<<<g4, 256>>>(xsel, Bim + (size_t)i * 65536, 1);
        scan_carry<<<BB * NC, 256>>>();
        scan_prefix<<<BB, 256>>>();
        scan_final<<<BB * NC, 256>>>();
        gemm_cproj<<<g4, 256>>>(Cre + (size_t)i * 65536, Cim + (size_t)i * 65536,
                                Dd + i * 256, xsel);
        gemm_glu<<<g8, 256>>>(W1 + (size_t)i * 256 * 1024, b1 + i * 1024);
        gemm_nn<1><<<g4, 256>>>(nullptr, 512, W2 + (size_t)i * 512 * 256, b2 + i * 256);
        xsel = 1;
    }
    pool1<<<BB * 8, 256>>>();
    pool2<<<BB, 256>>>();
    head<<<1, 320>>>(Wout, bout, (float*)d_out);
}

// round 6
// speedup vs baseline: 1.2850x; 1.2850x over previous
#include <cuda_runtime.h>
#include <cstdint>

// ---------------- problem constants ----------------
#define MTOT 65536
#define EF   256
#define HF   256
#define NBLK 6
#define TLEN 2048
#define BB   32
#define NC   32
#define TC   64

#define KC   16
#define SSTR 132

// ---------------- scratch ----------------
static __device__ float g_y[(size_t)MTOT * EF];
static __device__ float g_x[(size_t)MTOT * EF];
static __device__ float g_bure[(size_t)MTOT * HF];
static __device__ float g_buim[(size_t)MTOT * HF];
static __device__ float g_hre[(size_t)MTOT * HF];
static __device__ float g_him[(size_t)MTOT * HF];
static __device__ float g_u[(size_t)MTOT * EF];
static __device__ float g_g[(size_t)MTOT * 512];
static __device__ float g_part[256 * 512];
static __device__ float g_bna[EF], g_bnc[EF];
static __device__ float g_lr[HF], g_li[HF], g_gam[HF], g_L64r[HF], g_L64i[HF];
static __device__ float g_car_re[BB * NC * HF], g_car_im[BB * NC * HF];
static __device__ float g_pre_re[BB * NC * HF], g_pre_im[BB * NC * HF];
static __device__ float g_poolpart[BB * 8 * EF];
static __device__ float g_pool[BB * EF];

// ================= BN statistics =================
__global__ void __launch_bounds__(256) bn_stage1(int xsel) {
    const float* x = xsel ? g_x : g_y;
    int blk = blockIdx.x;
    int e = threadIdx.x;
    const float* p = x + (size_t)blk * 256 * EF + e;
    float s = 0.f, s2 = 0.f;
    for (int r = 0; r < 256; r++) {
        float v = p[(size_t)r * EF];
        s += v;
        s2 += v * v;
    }
    g_part[blk * 512 + e] = s;
    g_part[blk * 512 + 256 + e] = s2;
}
__global__ void __launch_bounds__(256) bn_stage2(const float* __restrict__ scale,
                                                 const float* __restrict__ bias) {
    int e = threadIdx.x;
    float s = 0.f, s2 = 0.f;
    for (int p = 0; p < 256; p++) {
        s += g_part[p * 512 + e];
        s2 += g_part[p * 512 + 256 + e];
    }
    const float inv = 1.0f / 65536.0f;
    float mu = s * inv;
    float var = fmaxf(s2 * inv - mu * mu, 0.0f);
    float a = rsqrtf(var + 1e-5f) * scale[e];
    g_bna[e] = a;
    g_bnc[e] = bias[e] - mu * a;
}

// ================= lambda / gamma =================
__global__ void lam_kernel(const float* __restrict__ nul, const float* __restrict__ thl) {
    int h = threadIdx.x;
    float nu = expf(nul[h]);
    float th = expf(thl[h]);
    float r = expf(-nu);
    float sn, cs;
    sincosf(th, &sn, &cs);
    float lr = r * cs, li = r * sn;
    g_lr[h] = lr;
    g_li[h] = li;
    g_gam[h] = sqrtf(fmaxf(1.0f - r * r, 1e-12f));
    float ar = lr, ai = li;
#pragma unroll
    for (int s = 0; s < 6; s++) {
        float nr = ar * ar - ai * ai;
        float ni = 2.0f * ar * ai;
        ar = nr;
        ai = ni;
    }
    g_L64r[h] = ar;
    g_L64i[h] = ai;
}

// ================= GEMM NN (encoder ROLE=0, MLP2+residual ROLE=1) =================
// out[M,256] = A[M,K] @ W[K,256] + bias (+ g_y if ROLE==1)
template <int ROLE>
__global__ void __launch_bounds__(256) gemm_nn(const float* __restrict__ Aext, int K,
                                               const float* __restrict__ W,
                                               const float* __restrict__ bias) {
    __shared__ __align__(16) float As[2][KC * SSTR];
    __shared__ __align__(16) float Bs[2][KC * SSTR];
    const float* A = (ROLE == 0) ? Aext : g_g;
    float* out = (ROLE == 0) ? g_y : g_x;
    const int tid = threadIdx.x;
    const int m0 = blockIdx.x * 128;
    const int n0 = blockIdx.y * 128;
    const int tx = tid & 15, ty = tid >> 4;
    const int arow = tid & 127, akh = (tid >> 7) * 8;
    const int bk = tid >> 4, bn = (tid & 15) * 4;
    const int nch = K / KC;

    float4 fa0, fa1, fb0, fb1;
    auto fetch = [&](int c) {
        int kc = c * KC;
        const float* ap = A + (size_t)(m0 + arow) * K + kc + akh;
        fa0 = *(const float4*)ap;
        fa1 = *(const float4*)(ap + 4);
        const float* bp = W + (size_t)(kc + bk) * 256 + n0 + bn;
        fb0 = *(const float4*)bp;
        fb1 = *(const float4*)(bp + 64);
    };
    auto store = [&](int buf) {
        float* a = As[buf];
        a[(akh + 0) * SSTR + arow] = fa0.x; a[(akh + 1) * SSTR + arow] = fa0.y;
        a[(akh + 2) * SSTR + arow] = fa0.z; a[(akh + 3) * SSTR + arow] = fa0.w;
        a[(akh + 4) * SSTR + arow] = fa1.x; a[(akh + 5) * SSTR + arow] = fa1.y;
        a[(akh + 6) * SSTR + arow] = fa1.z; a[(akh + 7) * SSTR + arow] = fa1.w;
        float* b = Bs[buf];
        *(float4*)&b[bk * SSTR + bn] = fb0;
        *(float4*)&b[bk * SSTR + bn + 64] = fb1;
    };

    float acc[2][2][4][4];
#pragma unroll
    for (int p = 0; p < 2; p++)
#pragma unroll
        for (int q = 0; q < 2; q++)
#pragma unroll
            for (int i = 0; i < 4; i++)
#pragma unroll
                for (int j = 0; j < 4; j++) acc[p][q][i][j] = 0.f;

    fetch(0);
    store(0);
    __syncthreads();
    for (int c = 0; c < nch; c++) {
        if (c + 1 < nch) fetch(c + 1);
        const float* as = As[c & 1];
        const float* bs = Bs[c & 1];
#pragma unroll
        for (int kk = 0; kk < KC; kk++) {
            float4 a0 = *(const float4*)&as[kk * SSTR + ty * 4];
            float4 a1 = *(const float4*)&as[kk * SSTR + ty * 4 + 64];
            float4 b0 = *(const float4*)&bs[kk * SSTR + tx * 4];
            float4 b1 = *(const float4*)&bs[kk * SSTR + tx * 4 + 64];
            float av[8] = {a0.x, a0.y, a0.z, a0.w, a1.x, a1.y, a1.z, a1.w};
            float bv[8] = {b0.x, b0.y, b0.z, b0.w, b1.x, b1.y, b1.z, b1.w};
#pragma unroll
            for (int rg = 0; rg < 2; rg++)
#pragma unroll
                for (int i = 0; i < 4; i++)
#pragma unroll
                    for (int cg = 0; cg < 2; cg++)
#pragma unroll
                        for (int j = 0; j < 4; j++)
                            acc[rg][cg][i][j] = fmaf(av[rg * 4 + i], bv[cg * 4 + j],
                                                     acc[rg][cg][i][j]);
        }
        if (c + 1 < nch) store((c + 1) & 1);
        __syncthreads();
    }

#pragma unroll
    for (int rg = 0; rg < 2; rg++)
#pragma unroll
        for (int i = 0; i < 4; i++) {
            size_t row = (size_t)(m0 + rg * 64 + ty * 4 + i);
#pragma unroll
            for (int cg = 0; cg < 2; cg++) {
                int n = n0 + cg * 64 + tx * 4;
                float4 bq = *(const float4*)(bias + n);
                float4 o;
                o.x = acc[rg][cg][i][0] + bq.x;
                o.y = acc[rg][cg][i][1] + bq.y;
                o.z = acc[rg][cg][i][2] + bq.z;
                o.w = acc[rg][cg][i][3] + bq.w;
                if (ROLE == 1) {
                    float4 yv = *(const float4*)(g_y + row * 256 + n);
                    o.x += yv.x; o.y += yv.y; o.z += yv.z; o.w += yv.w;
                }
                *(float4*)(out + row * 256 + n) = o;
            }
        }
}

// ================= GEMM Bu (TN): out = BN(A) @ W^T * gamma =================
__global__ void __launch_bounds__(256) gemm_bu(int xsel, const float* __restrict__ W,
                                               int osel) {
    __shared__ __align__(16) float As[2][KC * SSTR];
    __shared__ __align__(16) float Bs[2][KC * SSTR];
    const float* A = xsel ? g_x : g_y;
    float* out = osel ? g_buim : g_bure;
    const int tid = threadIdx.x;
    const int m0 = blockIdx.x * 128;
    const int n0 = blockIdx.y * 128;
    const int tx = tid & 15, ty = tid >> 4;
    const int arow = tid & 127, akh = (tid >> 7) * 8;

    float4 fa0, fa1, fb0, fb1;
    auto fetch = [&](int c) {
        int kc = c * KC;
        const float* ap = A + (size_t)(m0 + arow) * 256 + kc + akh;
        fa0 = *(const float4*)ap;
        fa1 = *(const float4*)(ap + 4);
        float4 ba0 = *(const float4*)(g_bna + kc + akh);
        float4 ba1 = *(const float4*)(g_bna + kc + akh + 4);
        float4 bc0 = *(const float4*)(g_bnc + kc + akh);
        float4 bc1 = *(const float4*)(g_bnc + kc + akh + 4);
        fa0.x = fmaf(ba0.x, fa0.x, bc0.x); fa0.y = fmaf(ba0.y, fa0.y, bc0.y);
        fa0.z = fmaf(ba0.z, fa0.z, bc0.z); fa0.w = fmaf(ba0.w, fa0.w, bc0.w);
        fa1.x = fmaf(ba1.x, fa1.x, bc1.x); fa1.y = fmaf(ba1.y, fa1.y, bc1.y);
        fa1.z = fmaf(ba1.z, fa1.z, bc1.z); fa1.w = fmaf(ba1.w, fa1.w, bc1.w);
        const float* bp = W + (size_t)(n0 + arow) * 256 + kc + akh;
        fb0 = *(const float4*)bp;
        fb1 = *(const float4*)(bp + 4);
    };
    auto store = [&](int buf) {
        float* a = As[buf];
        a[(akh + 0) * SSTR + arow] = fa0.x; a[(akh + 1) * SSTR + arow] = fa0.y;
        a[(akh + 2) * SSTR + arow] = fa0.z; a[(akh + 3) * SSTR + arow] = fa0.w;
        a[(akh + 4) * SSTR + arow] = fa1.x; a[(akh + 5) * SSTR + arow] = fa1.y;
        a[(akh + 6) * SSTR + arow] = fa1.z; a[(akh + 7) * SSTR + arow] = fa1.w;
        float* b = Bs[buf];
        b[(akh + 0) * SSTR + arow] = fb0.x; b[(akh + 1) * SSTR + arow] = fb0.y;
        b[(akh + 2) * SSTR + arow] = fb0.z; b[(akh + 3) * SSTR + arow] = fb0.w;
        b[(akh + 4) * SSTR + arow] = fb1.x; b[(akh + 5) * SSTR + arow] = fb1.y;
        b[(akh + 6) * SSTR + arow] = fb1.z; b[(akh + 7) * SSTR + arow] = fb1.w;
    };

    float acc[2][2][4][4];
#pragma unroll
    for (int p = 0; p < 2; p++)
#pragma unroll
        for (int q = 0; q < 2; q++)
#pragma unroll
            for (int i = 0; i < 4; i++)
#pragma unroll
                for (int j = 0; j < 4; j++) acc[p][q][i][j] = 0.f;

    fetch(0);
    store(0);
    __syncthreads();
    for (int c = 0; c < 16; c++) {
        if (c + 1 < 16) fetch(c + 1);
        const float* as = As[c & 1];
        const float* bs = Bs[c & 1];
#pragma unroll
        for (int kk = 0; kk < KC; kk++) {
            float4 a0 = *(const float4*)&as[kk * SSTR + ty * 4];
            float4 a1 = *(const float4*)&as[kk * SSTR + ty * 4 + 64];
            float4 b0 = *(const float4*)&bs[kk * SSTR + tx * 4];
            float4 b1 = *(const float4*)&bs[kk * SSTR + tx * 4 + 64];
            float av[8] = {a0.x, a0.y, a0.z, a0.w, a1.x, a1.y, a1.z, a1.w};
            float bv[8] = {b0.x, b0.y, b0.z, b0.w, b1.x, b1.y, b1.z, b1.w};
#pragma unroll
            for (int rg = 0; rg < 2; rg++)
#pragma unroll
                for (int i = 0; i < 4; i++)
#pragma unroll
                    for (int cg = 0; cg < 2; cg++)
#pragma unroll
                        for (int j = 0; j < 4; j++)
                            acc[rg][cg][i][j] = fmaf(av[rg * 4 + i], bv[cg * 4 + j],
                                                     acc[rg][cg][i][j]);
        }
        if (c + 1 < 16) store((c + 1) & 1);
        __syncthreads();
    }

#pragma unroll
    for (int rg = 0; rg < 2; rg++)
#pragma unroll
        for (int i = 0; i < 4; i++) {
            size_t row = (size_t)(m0 + rg * 64 + ty * 4 + i);
#pragma unroll
            for (int cg = 0; cg < 2; cg++) {
                int n = n0 + cg * 64 + tx * 4;
                float4 gm = *(const float4*)(g_gam + n);
                float4 o;
                o.x = acc[rg][cg][i][0] * gm.x;
                o.y = acc[rg][cg][i][1] * gm.y;
                o.z = acc[rg][cg][i][2] * gm.z;
                o.w = acc[rg][cg][i][3] * gm.w;
                *(float4*)(out + row * 256 + n) = o;
            }
        }
}

// ================= GEMM cproj (dual TN): u = hre@Cre^T - him@Cim^T + D*BN(x) ==========
#define KC2 8
__global__ void __launch_bounds__(256) gemm_cproj(const float* __restrict__ Wr,
                                                  const float* __restrict__ Wi,
                                                  const float* __restrict__ Dv, int xsel) {
    __shared__ __align__(16) float Asr[2][KC2 * SSTR];
    __shared__ __align__(16) float Asi[2][KC2 * SSTR];
    __shared__ __align__(16) float Bsr[2][KC2 * SSTR];
    __shared__ __align__(16) float Bsi[2][KC2 * SSTR];
    const float* Xin = xsel ? g_x : g_y;
    const int tid = threadIdx.x;
    const int m0 = blockIdx.x * 128;
    const int n0 = blockIdx.y * 128;
    const int tx = tid & 15, ty = tid >> 4;
    const int arow = tid & 127, akh = (tid >> 7) * 4;

    float4 fr, fi, fwr, fwi;
    auto fetch = [&](int c) {
        int kc = c * KC2;
        fr = *(const float4*)(g_hre + (size_t)(m0 + arow) * 256 + kc + akh);
        fi = *(const float4*)(g_him + (size_t)(m0 + arow) * 256 + kc + akh);
        fwr = *(const float4*)(Wr + (size_t)(n0 + arow) * 256 + kc + akh);
        fwi = *(const float4*)(Wi + (size_t)(n0 + arow) * 256 + kc + akh);
    };
    auto store = [&](int buf) {
        float* ar = Asr[buf];
        float* ai = Asi[buf];
        float* br = Bsr[buf];
        float* bi = Bsi[buf];
        ar[(akh + 0) * SSTR + arow] = fr.x; ar[(akh + 1) * SSTR + arow] = fr.y;
        ar[(akh + 2) * SSTR + arow] = fr.z; ar[(akh + 3) * SSTR + arow] = fr.w;
        ai[(akh + 0) * SSTR + arow] = fi.x; ai[(akh + 1) * SSTR + arow] = fi.y;
        ai[(akh + 2) * SSTR + arow] = fi.z; ai[(akh + 3) * SSTR + arow] = fi.w;
        br[(akh + 0) * SSTR + arow] = fwr.x; br[(akh + 1) * SSTR + arow] = fwr.y;
        br[(akh + 2) * SSTR + arow] = fwr.z; br[(akh + 3) * SSTR + arow] = fwr.w;
        bi[(akh + 0) * SSTR + arow] = -fwi.x; bi[(akh + 1) * SSTR + arow] = -fwi.y;
        bi[(akh + 2) * SSTR + arow] = -fwi.z; bi[(akh + 3) * SSTR + arow] = -fwi.w;
    };

    float acc[2][2][4][4];
#pragma unroll
    for (int p = 0; p < 2; p++)
#pragma unroll
        for (int q = 0; q < 2; q++)
#pragma unroll
            for (int i = 0; i < 4; i++)
#pragma unroll
                for (int j = 0; j < 4; j++) acc[p][q][i][j] = 0.f;

    fetch(0);
    store(0);
    __syncthreads();
    for (int c = 0; c < 32; c++) {
        if (c + 1 < 32) fetch(c + 1);
        const float* ars = Asr[c & 1];
        const float* ais = Asi[c & 1];
        const float* brs = Bsr[c & 1];
        const float* bis = Bsi[c & 1];
#pragma unroll
        for (int kk = 0; kk < KC2; kk++) {
            float4 r0 = *(const float4*)&ars[kk * SSTR + ty * 4];
            float4 r1 = *(const float4*)&ars[kk * SSTR + ty * 4 + 64];
            float4 i0 = *(const float4*)&ais[kk * SSTR + ty * 4];
            float4 i1 = *(const float4*)&ais[kk * SSTR + ty * 4 + 64];
            float4 p0 = *(const float4*)&brs[kk * SSTR + tx * 4];
            float4 p1 = *(const float4*)&brs[kk * SSTR + tx * 4 + 64];
            float4 q0 = *(const float4*)&bis[kk * SSTR + tx * 4];
            float4 q1 = *(const float4*)&bis[kk * SSTR + tx * 4 + 64];
            float arv[8] = {r0.x, r0.y, r0.z, r0.w, r1.x, r1.y, r1.z, r1.w};
            float aiv[8] = {i0.x, i0.y, i0.z, i0.w, i1.x, i1.y, i1.z, i1.w};
            float brv[8] = {p0.x, p0.y, p0.z, p0.w, p1.x, p1.y, p1.z, p1.w};
            float biv[8] = {q0.x, q0.y, q0.z, q0.w, q1.x, q1.y, q1.z, q1.w};
#pragma unroll
            for (int rg = 0; rg < 2; rg++)
#pragma unroll
                for (int i = 0; i < 4; i++)
#pragma unroll
                    for (int cg = 0; cg < 2; cg++)
#pragma unroll
                        for (int j = 0; j < 4; j++) {
                            float t = fmaf(arv[rg * 4 + i], brv[cg * 4 + j],
                                           acc[rg][cg][i][j]);
                            acc[rg][cg][i][j] = fmaf(aiv[rg * 4 + i], biv[cg * 4 + j], t);
                        }
        }
        if (c + 1 < 32) store((c + 1) & 1);
        __syncthreads();
    }

#pragma unroll
    for (int rg = 0; rg < 2; rg++)
#pragma unroll
        for (int i = 0; i < 4; i++) {
            size_t row = (size_t)(m0 + rg * 64 + ty * 4 + i);
#pragma unroll
            for (int cg = 0; cg < 2; cg++) {
                int n = n0 + cg * 64 + tx * 4;
                float4 dq = *(const float4*)(Dv + n);
                float4 ba = *(const float4*)(g_bna + n);
                float4 bc = *(const float4*)(g_bnc + n);
                float4 xv = *(const float4*)(Xin + row * 256 + n);
                float4 o;
                o.x = acc[rg][cg][i][0] + dq.x * fmaf(ba.x, xv.x, bc.x);
                o.y = acc[rg][cg][i][1] + dq.y * fmaf(ba.y, xv.y, bc.y);
                o.z = acc[rg][cg][i][2] + dq.z * fmaf(ba.z, xv.z, bc.z);
                o.w = acc[rg][cg][i][3] + dq.w * fmaf(ba.w, xv.w, bc.w);
                *(float4*)(g_u + row * 256 + n) = o;
            }
        }
}

// ================= GEMM GLU (NN, paired cols): g = GLU(u @ W1 + b1) =================
__global__ void __launch_bounds__(256) gemm_glu(const float* __restrict__ W1,
                                                const float* __restrict__ b1) {
    __shared__ __align__(16) float As[2][KC * SSTR];
    __shared__ __align__(16) float Bs[2][KC * SSTR];
    const int tid = threadIdx.x;
    const int m0 = blockIdx.x * 128;
    const int n0 = blockIdx.y * 64;      // 64 output cols per block
    const int tx = tid & 15, ty = tid >> 4;
    const int arow = tid & 127, akh = (tid >> 7) * 8;
    const int bk = tid >> 4, bn = (tid & 15) * 4;

    float4 fa0, fa1, fb0, fb1;
    auto fetch = [&](int c) {
        int kc = c * KC;
        const float* ap = g_u + (size_t)(m0 + arow) * 256 + kc + akh;
        fa0 = *(const float4*)ap;
        fa1 = *(const float4*)(ap + 4);
        const float* bp = W1 + (size_t)(kc + bk) * 1024;
        fb0 = *(const float4*)(bp + n0 + bn);
        fb1 = *(const float4*)(bp + 512 + n0 + bn);
    };
    auto store = [&](int buf) {
        float* a = As[buf];
        a[(akh + 0) * SSTR + arow] = fa0.x; a[(akh + 1) * SSTR + arow] = fa0.y;
        a[(akh + 2) * SSTR + arow] = fa0.z; a[(akh + 3) * SSTR + arow] = fa0.w;
        a[(akh + 4) * SSTR + arow] = fa1.x; a[(akh + 5) * SSTR + arow] = fa1.y;
        a[(akh + 6) * SSTR + arow] = fa1.z; a[(akh + 7) * SSTR + arow] = fa1.w;
        float* b = Bs[buf];
        *(float4*)&b[bk * SSTR + bn] = fb0;
        *(float4*)&b[bk * SSTR + bn + 64] = fb1;
    };

    float acc[2][2][4][4];
#pragma unroll
    for (int p = 0; p < 2; p++)
#pragma unroll
        for (int q = 0; q < 2; q++)
#pragma unroll
            for (int i = 0; i < 4; i++)
#pragma unroll
                for (int j = 0; j < 4; j++) acc[p][q][i][j] = 0.f;

    fetch(0);
    store(0);
    __syncthreads();
    for (int c = 0; c < 16; c++) {
        if (c + 1 < 16) fetch(c + 1);
        const float* as = As[c & 1];
        const float* bs = Bs[c & 1];
#pragma unroll
        for (int kk = 0; kk < KC; kk++) {
            float4 a0 = *(const float4*)&as[kk * SSTR + ty * 4];
            float4 a1 = *(const float4*)&as[kk * SSTR + ty * 4 + 64];
            float4 b0 = *(const float4*)&bs[kk * SSTR + tx * 4];
            float4 b1 = *(const float4*)&bs[kk * SSTR + tx * 4 + 64];
            float av[8] = {a0.x, a0.y, a0.z, a0.w, a1.x, a1.y, a1.z, a1.w};
            float bv[8] = {b0.x, b0.y, b0.z, b0.w, b1.x, b1.y, b1.z, b1.w};
#pragma unroll
            for (int rg = 0; rg < 2; rg++)
#pragma unroll
                for (int i = 0; i < 4; i++)
#pragma unroll
                    for (int cg = 0; cg < 2; cg++)
#pragma unroll
                        for (int j = 0; j < 4; j++)
                            acc[rg][cg][i][j] = fmaf(av[rg * 4 + i], bv[cg * 4 + j],
                                                     acc[rg][cg][i][j]);
        }
        if (c + 1 < 16) store((c + 1) & 1);
        __syncthreads();
    }

    int n = n0 + tx * 4;
    float4 b1a = *(const float4*)(b1 + n);
    float4 b1b = *(const float4*)(b1 + 512 + n);
#pragma unroll
    for (int rg = 0; rg < 2; rg++)
#pragma unroll
        for (int i = 0; i < 4; i++) {
            size_t row = (size_t)(m0 + rg * 64 + ty * 4 + i);
            float za0 = acc[rg][0][i][0] + b1a.x;
            float za1 = acc[rg][0][i][1] + b1a.y;
            float za2 = acc[rg][0][i][2] + b1a.z;
            float za3 = acc[rg][0][i][3] + b1a.w;
            float zb0 = acc[rg][1][i][0] + b1b.x;
            float zb1 = acc[rg][1][i][1] + b1b.y;
            float zb2 = acc[rg][1][i][2] + b1b.z;
            float zb3 = acc[rg][1][i][3] + b1b.w;
            float4 o;
            o.x = __fdividef(za0, 1.0f + __expf(-zb0));
            o.y = __fdividef(za1, 1.0f + __expf(-zb1));
            o.z = __fdividef(za2, 1.0f + __expf(-zb2));
            o.w = __fdividef(za3, 1.0f + __expf(-zb3));
            *(float4*)(g_g + row * 512 + n) = o;
        }
}

// ================= chunked scan =================
__global__ void __launch_bounds__(256) scan_carry() {
    int h = threadIdx.x;
    int c = blockIdx.x & 31;
    int b = blockIdx.x >> 5;
    float lr = g_lr[h], li = g_li[h];
    float hr = 0.f, hi = 0.f;
    size_t base = ((size_t)b * TLEN + c * TC) * HF + h;
#pragma unroll 4
    for (int t = 0; t < TC; t++) {
        float ur = g_bure[base + (size_t)t * HF];
        float ui = g_buim[base + (size_t)t * HF];
        float nr = fmaf(lr, hr, fmaf(-li, hi, ur));
        float ni = fmaf(lr, hi, fmaf(li, hr, ui));
        hr = nr;
        hi = ni;
    }
    int ci = (b * NC + c) * HF + h;
    g_car_re[ci] = hr;
    g_car_im[ci] = hi;
}
__global__ void __launch_bounds__(256) scan_prefix() {
    int h = threadIdx.x;
    int b = blockIdx.x;
    float Lr = g_L64r[h], Li = g_L64i[h];
    float Hr = 0.f, Hi = 0.f;
    for (int c = 0; c < NC; c++) {
        int ci = (b * NC + c) * HF + h;
        g_pre_re[ci] = Hr;
        g_pre_im[ci] = Hi;
        float cr = g_car_re[ci], cim = g_car_im[ci];
        float nr = fmaf(Lr, Hr, fmaf(-Li, Hi, cr));
        float ni = fmaf(Lr, Hi, fmaf(Li, Hr, cim));
        Hr = nr;
        Hi = ni;
    }
}
__global__ void __launch_bounds__(256) scan_final() {
    int h = threadIdx.x;
    int c = blockIdx.x & 31;
    int b = blockIdx.x >> 5;
    float lr = g_lr[h], li = g_li[h];
    int ci = (b * NC + c) * HF + h;
    float hr = g_pre_re[ci], hi = g_pre_im[ci];
    size_t base = ((size_t)b * TLEN + c * TC) * HF + h;
#pragma unroll 4
    for (int t = 0; t < TC; t++) {
        size_t idx = base + (size_t)t * HF;
        float ur = g_bure[idx];
        float ui = g_buim[idx];
        float nr = fmaf(lr, hr, fmaf(-li, hi, ur));
        float ni = fmaf(lr, hi, fmaf(li, hr, ui));
        hr = nr;
        hi = ni;
        g_hre[idx] = hr;
        g_him[idx] = hi;
    }
}

// ================= pool + head =================
__global__ void __launch_bounds__(256) pool1() {
    int b = blockIdx.x >> 3;
    int c = blockIdx.x & 7;
    int e = threadIdx.x;
    const float* p = g_x + ((size_t)b * TLEN + c * 256) * EF + e;
    float s = 0.f;
#pragma unroll 8
    for (int t = 0; t < 256; t++) s += p[(size_t)t * EF];
    g_poolpart[(b * 8 + c) * EF + e] = s;
}
__global__ void __launch_bounds__(256) pool2() {
    int b = blockIdx.x;
    int e = threadIdx.x;
    float s = 0.f;
    for (int c = 0; c < 8; c++) s += g_poolpart[(b * 8 + c) * EF + e];
    g_pool[b * EF + e] = s * (1.0f / (float)TLEN);
}
__global__ void head(const float* __restrict__ Wout, const float* __restrict__ bout,
                     float* __restrict__ out) {
    int tid = threadIdx.x;
    if (tid >= 320) return;
    int b = tid / 10;
    int o = tid % 10;
    float s = bout[o];
    const float* p = g_pool + b * EF;
    for (int e = 0; e < 256; e++) s = fmaf(p[e], Wout[e * 10 + o], s);
    out[b * 10 + o] = s;
}

// ================= host orchestration =================
extern "C" void kernel_launch(void* const* d_in, const int* in_sizes, int n_in,
                              void* d_out, int out_size) {
    const float* x    = (const float*)d_in[0];
    const float* Wenc = (const float*)d_in[1];
    const float* benc = (const float*)d_in[2];
    const float* nul  = (const float*)d_in[3];
    const float* thl  = (const float*)d_in[4];
    const float* Bre  = (const float*)d_in[5];
    const float* Bim  = (const float*)d_in[6];
    const float* Cre  = (const float*)d_in[7];
    const float* Cim  = (const float*)d_in[8];
    const float* Dd   = (const float*)d_in[9];
    const float* W1   = (const float*)d_in[10];
    const float* b1   = (const float*)d_in[11];
    const float* W2   = (const float*)d_in[12];
    const float* b2   = (const float*)d_in[13];
    const float* bns  = (const float*)d_in[14];
    const float* bnb  = (const float*)d_in[15];
    const float* Wout = (const float*)d_in[16];
    const float* bout = (const float*)d_in[17];

    dim3 g2(512, 2), g8(512, 8);

    // encoder: y = x @ W_enc + b_enc
    gemm_nn<0><<<g2, 256>>>(x, 64, Wenc, benc);

    int xsel = 0;
    for (int i = 0; i < NBLK; i++) {
        bn_stage1<<<256, 256>>>(xsel);
        bn_stage2<<<1, 256>>>(bns + i * 256, bnb + i * 256);
        lam_kernel<<<1, 256>>>(nul + i * 256, thl + i * 256);
        gemm_bu<<<g2, 256>>>(xsel, Bre + (size_t)i * 65536, 0);
        gemm_bu<<<g2, 256>>>(xsel, Bim + (size_t)i * 65536, 1);
        scan_carry<<<BB * NC, 256>>>();
        scan_prefix<<<BB, 256>>>();
        scan_final<<<BB * NC, 256>>>();
        gemm_cproj<<<g2, 256>>>(Cre + (size_t)i * 65536, Cim + (size_t)i * 65536,
                                Dd + i * 256, xsel);
        gemm_glu<<<g8, 256>>>(W1 + (size_t)i * 256 * 1024, b1 + i * 1024);
        gemm_nn<1><<<g2, 256>>>(nullptr, 512, W2 + (size_t)i * 512 * 256, b2 + i * 256);
        xsel = 1;
    }
    pool1<<<BB * 8, 256>>>();
    pool2<<<BB, 256>>>();
    head<<<1, 320>>>(Wout, bout, (float*)d_out);
}

// round 7
// speedup vs baseline: 1.3472x; 1.0485x over previous
#include <cuda_runtime.h>

// ---------------- problem constants ----------------
#define MTOT 65536      // B*T tokens
#define EF   256        // E features
#define HF   256        // H state size
#define LF   1024       // MLP hidden (pre-GLU)
#define NBLK 6
#define TLEN 2048
#define BB   32
#define NC   32         // scan chunks
#define TC   64         // chunk length (NC*TC == TLEN)

// ---------------- scratch (device globals; no allocation allowed) ----------------
static __device__ float g_y[(size_t)MTOT * EF];      // encoder output / residual anchor
static __device__ float g_x[(size_t)MTOT * EF];      // current block output
static __device__ float g_bure[(size_t)MTOT * HF];
static __device__ float g_buim[(size_t)MTOT * HF];
static __device__ float g_hre[(size_t)MTOT * HF];
static __device__ float g_him[(size_t)MTOT * HF];
static __device__ float g_u[(size_t)MTOT * EF];
static __device__ float g_g[(size_t)MTOT * (LF / 2)];
static __device__ float g_part[512 * 512];           // BN partials: [512 m-blocks][256 sum | 256 sumsq]
static __device__ float g_bna[EF];                   // BN fold: a = rsqrt(var+eps)*scale
static __device__ float g_bnc[EF];                   // BN fold: c = bias - mu*a
static __device__ float g_lr[HF], g_li[HF], g_gam[HF], g_L64r[HF], g_L64i[HF];
static __device__ float g_car_re[BB * NC * HF], g_car_im[BB * NC * HF];
static __device__ float g_pre_re[BB * NC * HF], g_pre_im[BB * NC * HF];
static __device__ float g_poolpart[BB * 8 * EF];
static __device__ float g_pool[BB * EF];

// ================= BN finalize (partials produced by GEMM epilogues) =================
__global__ void __launch_bounds__(256) bn_stage2(const float* __restrict__ scale,
                                                 const float* __restrict__ bias) {
    int e = threadIdx.x;
    float s = 0.f, s2 = 0.f;
    for (int p = 0; p < 512; p++) {
        s += g_part[p * 512 + e];
        s2 += g_part[p * 512 + 256 + e];
    }
    const float inv = 1.0f / 65536.0f;
    float mu = s * inv;
    float var = fmaxf(s2 * inv - mu * mu, 0.0f);
    float a = rsqrtf(var + 1e-5f) * scale[e];
    g_bna[e] = a;
    g_bnc[e] = bias[e] - mu * a;
}

// ================= lambda / gamma precompute =================
__global__ void lam_kernel(const float* __restrict__ nul, const float* __restrict__ thl) {
    int h = threadIdx.x;
    float nu = expf(nul[h]);
    float th = expf(thl[h]);
    float r = expf(-nu);
    float sn, cs;
    sincosf(th, &sn, &cs);
    float lr = r * cs, li = r * sn;
    g_lr[h] = lr;
    g_li[h] = li;
    g_gam[h] = sqrtf(fmaxf(1.0f - r * r, 1e-12f));
    // lam^64 via 6 squarings
    float ar = lr, ai = li;
#pragma unroll
    for (int s = 0; s < 6; s++) {
        float nr = ar * ar - ai * ai;
        float ni = 2.0f * ar * ai;
        ar = nr;
        ai = ni;
    }
    g_L64r[h] = ar;
    g_L64i[h] = ai;
}

// ================= GEMM: Bu = BN(x) @ B^T * gamma  (TN, BN folded into A load) =================
// A: [M,256] row-major (raw x, BN applied on the fly). W: [256,256] row-major over K.
__global__ void __launch_bounds__(256) gemm_bu(int xsel, const float* __restrict__ W, int osel) {
    const float* A = xsel ? g_x : g_y;
    float* out = osel ? g_buim : g_bure;
    __shared__ __align__(16) float As[16][128];
    __shared__ __align__(16) float Bs[16][64];
    const int tid = threadIdx.x;
    const int m0 = blockIdx.x * 128;
    const int n0 = blockIdx.y * 64;
    const int tx = tid & 15;
    const int ty = tid >> 4;
    const int lr = tid >> 2;
    const int lk = (tid & 3) * 4;
    float acc[8][4];
#pragma unroll
    for (int j = 0; j < 8; j++)
#pragma unroll
        for (int i = 0; i < 4; i++) acc[j][i] = 0.f;

    for (int k0 = 0; k0 < 256; k0 += 16) {
        float4 a0 = *(const float4*)(A + (size_t)(m0 + lr) * 256 + k0 + lk);
        float4 a1 = *(const float4*)(A + (size_t)(m0 + lr + 64) * 256 + k0 + lk);
        float4 wv = *(const float4*)(W + (size_t)(n0 + lr) * 256 + k0 + lk);
        float4 ba = *(const float4*)(g_bna + k0 + lk);
        float4 bc = *(const float4*)(g_bnc + k0 + lk);
        a0.x = fmaf(ba.x, a0.x, bc.x); a0.y = fmaf(ba.y, a0.y, bc.y);
        a0.z = fmaf(ba.z, a0.z, bc.z); a0.w = fmaf(ba.w, a0.w, bc.w);
        a1.x = fmaf(ba.x, a1.x, bc.x); a1.y = fmaf(ba.y, a1.y, bc.y);
        a1.z = fmaf(ba.z, a1.z, bc.z); a1.w = fmaf(ba.w, a1.w, bc.w);
        __syncthreads();
        As[lk + 0][lr] = a0.x; As[lk + 1][lr] = a0.y; As[lk + 2][lr] = a0.z; As[lk + 3][lr] = a0.w;
        As[lk + 0][lr + 64] = a1.x; As[lk + 1][lr + 64] = a1.y;
        As[lk + 2][lr + 64] = a1.z; As[lk + 3][lr + 64] = a1.w;
        Bs[lk + 0][lr] = wv.x; Bs[lk + 1][lr] = wv.y; Bs[lk + 2][lr] = wv.z; Bs[lk + 3][lr] = wv.w;
        __syncthreads();
#pragma unroll
        for (int kk = 0; kk < 16; kk++) {
            float4 av0 = *(const float4*)&As[kk][ty * 8];
            float4 av1 = *(const float4*)&As[kk][ty * 8 + 4];
            float4 bv = *(const float4*)&Bs[kk][tx * 4];
            float a[8] = {av0.x, av0.y, av0.z, av0.w, av1.x, av1.y, av1.z, av1.w};
            float b[4] = {bv.x, bv.y, bv.z, bv.w};
#pragma unroll
            for (int j = 0; j < 8; j++)
#pragma unroll
                for (int i = 0; i < 4; i++) acc[j][i] = fmaf(a[j], b[i], acc[j][i]);
        }
    }
    float4 gm = *(const float4*)(g_gam + n0 + tx * 4);
#pragma unroll
    for (int j = 0; j < 8; j++) {
        float4 o;
        o.x = acc[j][0] * gm.x; o.y = acc[j][1] * gm.y;
        o.z = acc[j][2] * gm.z; o.w = acc[j][3] * gm.w;
        *(float4*)(out + (size_t)(m0 + ty * 8 + j) * 256 + n0 + tx * 4) = o;
    }
}

// ================= chunked scan =================
__global__ void __launch_bounds__(256) scan_carry() {
    int h = threadIdx.x;
    int c = blockIdx.x & 31;
    int b = blockIdx.x >> 5;
    float lr = g_lr[h], li = g_li[h];
    float hr = 0.f, hi = 0.f;
    size_t base = ((size_t)b * TLEN + c * TC) * HF + h;
#pragma unroll 4
    for (int t = 0; t < TC; t++) {
        float ur = g_bure[base + (size_t)t * HF];
        float ui = g_buim[base + (size_t)t * HF];
        float nr = fmaf(lr, hr, fmaf(-li, hi, ur));
        float ni = fmaf(lr, hi, fmaf(li, hr, ui));
        hr = nr;
        hi = ni;
    }
    int ci = (b * NC + c) * HF + h;
    g_car_re[ci] = hr;
    g_car_im[ci] = hi;
}

__global__ void __launch_bounds__(256) scan_prefix() {
    int h = threadIdx.x;
    int b = blockIdx.x;
    float Lr = g_L64r[h], Li = g_L64i[h];
    float Hr = 0.f, Hi = 0.f;
    for (int c = 0; c < NC; c++) {
        int ci = (b * NC + c) * HF + h;
        g_pre_re[ci] = Hr;
        g_pre_im[ci] = Hi;
        float cr = g_car_re[ci], cim = g_car_im[ci];
        float nr = fmaf(Lr, Hr, fmaf(-Li, Hi, cr));
        float ni = fmaf(Lr, Hi, fmaf(Li, Hr, cim));
        Hr = nr;
        Hi = ni;
    }
}

__global__ void __launch_bounds__(256) scan_final() {
    int h = threadIdx.x;
    int c = blockIdx.x & 31;
    int b = blockIdx.x >> 5;
    float lr = g_lr[h], li = g_li[h];
    int ci = (b * NC + c) * HF + h;
    float hr = g_pre_re[ci], hi = g_pre_im[ci];
    size_t base = ((size_t)b * TLEN + c * TC) * HF + h;
#pragma unroll 4
    for (int t = 0; t < TC; t++) {
        size_t idx = base + (size_t)t * HF;
        float ur = g_bure[idx];
        float ui = g_buim[idx];
        float nr = fmaf(lr, hr, fmaf(-li, hi, ur));
        float ni = fmaf(lr, hi, fmaf(li, hr, ui));
        hr = nr;
        hi = ni;
        g_hre[idx] = hr;
        g_him[idx] = hi;
    }
}

// ================= GEMM: u = Re(hs @ Cc) + D*BN(x)  (dual TN) =================
__global__ void __launch_bounds__(256) gemm_cproj(const float* __restrict__ Wr,
                                                  const float* __restrict__ Wi,
                                                  const float* __restrict__ Dv, int xsel) {
    const float* Xin = xsel ? g_x : g_y;
    __shared__ __align__(16) float Asr[16][128];
    __shared__ __align__(16) float Asi[16][128];
    __shared__ __align__(16) float Bsr[16][64];
    __shared__ __align__(16) float Bsi[16][64];
    const int tid = threadIdx.x;
    const int m0 = blockIdx.x * 128;
    const int n0 = blockIdx.y * 64;
    const int tx = tid & 15;
    const int ty = tid >> 4;
    const int lr = tid >> 2;
    const int lk = (tid & 3) * 4;
    float acc[8][4];
#pragma unroll
    for (int j = 0; j < 8; j++)
#pragma unroll
        for (int i = 0; i < 4; i++) acc[j][i] = 0.f;

    for (int k0 = 0; k0 < 256; k0 += 16) {
        float4 ar0 = *(const float4*)(g_hre + (size_t)(m0 + lr) * 256 + k0 + lk);
        float4 ar1 = *(const float4*)(g_hre + (size_t)(m0 + lr + 64) * 256 + k0 + lk);
        float4 ai0 = *(const float4*)(g_him + (size_t)(m0 + lr) * 256 + k0 + lk);
        float4 ai1 = *(const float4*)(g_him + (size_t)(m0 + lr + 64) * 256 + k0 + lk);
        float4 wr = *(const float4*)(Wr + (size_t)(n0 + lr) * 256 + k0 + lk);
        float4 wi = *(const float4*)(Wi + (size_t)(n0 + lr) * 256 + k0 + lk);
        __syncthreads();
        Asr[lk + 0][lr] = ar0.x; Asr[lk + 1][lr] = ar0.y; Asr[lk + 2][lr] = ar0.z; Asr[lk + 3][lr] = ar0.w;
        Asr[lk + 0][lr + 64] = ar1.x; Asr[lk + 1][lr + 64] = ar1.y;
        Asr[lk + 2][lr + 64] = ar1.z; Asr[lk + 3][lr + 64] = ar1.w;
        Asi[lk + 0][lr] = ai0.x; Asi[lk + 1][lr] = ai0.y; Asi[lk + 2][lr] = ai0.z; Asi[lk + 3][lr] = ai0.w;
        Asi[lk + 0][lr + 64] = ai1.x; Asi[lk + 1][lr + 64] = ai1.y;
        Asi[lk + 2][lr + 64] = ai1.z; Asi[lk + 3][lr + 64] = ai1.w;
        Bsr[lk + 0][lr] = wr.x; Bsr[lk + 1][lr] = wr.y; Bsr[lk + 2][lr] = wr.z; Bsr[lk + 3][lr] = wr.w;
        Bsi[lk + 0][lr] = wi.x; Bsi[lk + 1][lr] = wi.y; Bsi[lk + 2][lr] = wi.z; Bsi[lk + 3][lr] = wi.w;
        __syncthreads();
#pragma unroll
        for (int kk = 0; kk < 16; kk++) {
            float4 r0 = *(const float4*)&Asr[kk][ty * 8];
            float4 r1 = *(const float4*)&Asr[kk][ty * 8 + 4];
            float4 i0 = *(const float4*)&Asi[kk][ty * 8];
            float4 i1 = *(const float4*)&Asi[kk][ty * 8 + 4];
            float4 br = *(const float4*)&Bsr[kk][tx * 4];
            float4 bi = *(const float4*)&Bsi[kk][tx * 4];
            float arv[8] = {r0.x, r0.y, r0.z, r0.w, r1.x, r1.y, r1.z, r1.w};
            float aiv[8] = {i0.x, i0.y, i0.z, i0.w, i1.x, i1.y, i1.z, i1.w};
            float brv[4] = {br.x, br.y, br.z, br.w};
            float biv[4] = {bi.x, bi.y, bi.z, bi.w};
#pragma unroll
            for (int j = 0; j < 8; j++)
#pragma unroll
                for (int i = 0; i < 4; i++) {
                    acc[j][i] = fmaf(arv[j], brv[i], acc[j][i]);
                    acc[j][i] = fmaf(-aiv[j], biv[i], acc[j][i]);
                }
        }
    }
    float4 dq = *(const float4*)(Dv + n0 + tx * 4);
    float4 ba = *(const float4*)(g_bna + n0 + tx * 4);
    float4 bc = *(const float4*)(g_bnc + n0 + tx * 4);
#pragma unroll
    for (int j = 0; j < 8; j++) {
        size_t row = (size_t)(m0 + ty * 8 + j);
        float4 xv = *(const float4*)(Xin + row * 256 + n0 + tx * 4);
        float4 o;
        o.x = acc[j][0] + dq.x * fmaf(ba.x, xv.x, bc.x);
        o.y = acc[j][1] + dq.y * fmaf(ba.y, xv.y, bc.y);
        o.z = acc[j][2] + dq.z * fmaf(ba.z, xv.z, bc.z);
        o.w = acc[j][3] + dq.w * fmaf(ba.w, xv.w, bc.w);
        *(float4*)(g_u + row * 256 + n0 + tx * 4) = o;
    }
}

// ================= GEMM: g = GLU(u @ W1 + b1)   (NN, dual-B tile) =================
__global__ void __launch_bounds__(256) gemm_glu(const float* __restrict__ W1,
                                                const float* __restrict__ b1) {
    __shared__ __align__(16) float As[16][128];
    __shared__ __align__(16) float Ba[16][64];
    __shared__ __align__(16) float Bb[16][64];
    const int tid = threadIdx.x;
    const int m0 = blockIdx.x * 128;
    const int n0 = blockIdx.y * 64;  // 0..448 (within 512)
    const int tx = tid & 15;
    const int ty = tid >> 4;
    const int lr = tid >> 2;
    const int lk = (tid & 3) * 4;
    const int bk = tid >> 4;
    const int bn = (tid & 15) * 4;
    float acca[8][4], accb[8][4];
#pragma unroll
    for (int j = 0; j < 8; j++)
#pragma unroll
        for (int i = 0; i < 4; i++) { acca[j][i] = 0.f; accb[j][i] = 0.f; }

    for (int k0 = 0; k0 < 256; k0 += 16) {
        float4 a0 = *(const float4*)(g_u + (size_t)(m0 + lr) * 256 + k0 + lk);
        float4 a1 = *(const float4*)(g_u + (size_t)(m0 + lr + 64) * 256 + k0 + lk);
        float4 wa = *(const float4*)(W1 + (size_t)(k0 + bk) * 1024 + n0 + bn);
        float4 wb = *(const float4*)(W1 + (size_t)(k0 + bk) * 1024 + 512 + n0 + bn);
        __syncthreads();
        As[lk + 0][lr] = a0.x; As[lk + 1][lr] = a0.y; As[lk + 2][lr] = a0.z; As[lk + 3][lr] = a0.w;
        As[lk + 0][lr + 64] = a1.x; As[lk + 1][lr + 64] = a1.y;
        As[lk + 2][lr + 64] = a1.z; As[lk + 3][lr + 64] = a1.w;
        *(float4*)&Ba[bk][bn] = wa;
        *(float4*)&Bb[bk][bn] = wb;
        __syncthreads();
#pragma unroll
        for (int kk = 0; kk < 16; kk++) {
            float4 av0 = *(const float4*)&As[kk][ty * 8];
            float4 av1 = *(const float4*)&As[kk][ty * 8 + 4];
            float4 bva = *(const float4*)&Ba[kk][tx * 4];
            float4 bvb = *(const float4*)&Bb[kk][tx * 4];
            float a[8] = {av0.x, av0.y, av0.z, av0.w, av1.x, av1.y, av1.z, av1.w};
            float ba_[4] = {bva.x, bva.y, bva.z, bva.w};
            float bb_[4] = {bvb.x, bvb.y, bvb.z, bvb.w};
#pragma unroll
            for (int j = 0; j < 8; j++)
#pragma unroll
                for (int i = 0; i < 4; i++) {
                    acca[j][i] = fmaf(a[j], ba_[i], acca[j][i]);
                    accb[j][i] = fmaf(a[j], bb_[i], accb[j][i]);
                }
        }
    }
    float4 b1a = *(const float4*)(b1 + n0 + tx * 4);
    float4 b1b = *(const float4*)(b1 + 512 + n0 + tx * 4);
#pragma unroll
    for (int j = 0; j < 8; j++) {
        float za[4], zb[4];
        za[0] = acca[j][0] + b1a.x; za[1] = acca[j][1] + b1a.y;
        za[2] = acca[j][2] + b1a.z; za[3] = acca[j][3] + b1a.w;
        zb[0] = accb[j][0] + b1b.x; zb[1] = accb[j][1] + b1b.y;
        zb[2] = accb[j][2] + b1b.z; zb[3] = accb[j][3] + b1b.w;
        float4 o;
        o.x = __fdividef(za[0], 1.0f + __expf(-zb[0]));
        o.y = __fdividef(za[1], 1.0f + __expf(-zb[1]));
        o.z = __fdividef(za[2], 1.0f + __expf(-zb[2]));
        o.w = __fdividef(za[3], 1.0f + __expf(-zb[3]));
        *(float4*)(g_g + (size_t)(m0 + ty * 8 + j) * 512 + n0 + tx * 4) = o;
    }
}

// ================= GEMM NN (encoder: ROLE=0, MLP2+residual: ROLE=1) =================
// ROLE 0: out(g_y) = A_ext[M,K] @ B[K,256] + bias          (K=64)
// ROLE 1: out(g_x) = g_g[M,512] @ B[512,256] + bias + g_y  (K=512)
// Both epilogues also emit per-CTA BN partial sums (sum, sumsq) into g_part.
template <int ROLE>
__global__ void __launch_bounds__(256) gemm_nn(const float* __restrict__ Aext, int K,
                                               const float* __restrict__ B,
                                               const float* __restrict__ bias) {
    const float* A = (ROLE == 0) ? Aext : g_g;
    float* out = (ROLE == 0) ? g_y : g_x;
    __shared__ __align__(16) float As[16][128];
    __shared__ __align__(16) float Bs[16][64];
    const int tid = threadIdx.x;
    const int m0 = blockIdx.x * 128;
    const int n0 = blockIdx.y * 64;
    const int tx = tid & 15;
    const int ty = tid >> 4;
    const int lr = tid >> 2;
    const int lk = (tid & 3) * 4;
    const int bk = tid >> 4;
    const int bn = (tid & 15) * 4;
    float acc[8][4];
#pragma unroll
    for (int j = 0; j < 8; j++)
#pragma unroll
        for (int i = 0; i < 4; i++) acc[j][i] = 0.f;

    for (int k0 = 0; k0 < K; k0 += 16) {
        float4 a0 = *(const float4*)(A + (size_t)(m0 + lr) * K + k0 + lk);
        float4 a1 = *(const float4*)(A + (size_t)(m0 + lr + 64) * K + k0 + lk);
        float4 wv = *(const float4*)(B + (size_t)(k0 + bk) * 256 + n0 + bn);
        __syncthreads();
        As[lk + 0][lr] = a0.x; As[lk + 1][lr] = a0.y; As[lk + 2][lr] = a0.z; As[lk + 3][lr] = a0.w;
        As[lk + 0][lr + 64] = a1.x; As[lk + 1][lr + 64] = a1.y;
        As[lk + 2][lr + 64] = a1.z; As[lk + 3][lr + 64] = a1.w;
        *(float4*)&Bs[bk][bn] = wv;
        __syncthreads();
#pragma unroll
        for (int kk = 0; kk < 16; kk++) {
            float4 av0 = *(const float4*)&As[kk][ty * 8];
            float4 av1 = *(const float4*)&As[kk][ty * 8 + 4];
            float4 bv = *(const float4*)&Bs[kk][tx * 4];
            float a[8] = {av0.x, av0.y, av0.z, av0.w, av1.x, av1.y, av1.z, av1.w};
            float b[4] = {bv.x, bv.y, bv.z, bv.w};
#pragma unroll
            for (int j = 0; j < 8; j++)
#pragma unroll
                for (int i = 0; i < 4; i++) acc[j][i] = fmaf(a[j], b[i], acc[j][i]);
        }
    }
    float4 bq = *(const float4*)(bias + n0 + tx * 4);
    float ls[4] = {0.f, 0.f, 0.f, 0.f};
    float ls2[4] = {0.f, 0.f, 0.f, 0.f};
#pragma unroll
    for (int j = 0; j < 8; j++) {
        size_t row = (size_t)(m0 + ty * 8 + j);
        float4 o;
        o.x = acc[j][0] + bq.x; o.y = acc[j][1] + bq.y;
        o.z = acc[j][2] + bq.z; o.w = acc[j][3] + bq.w;
        if (ROLE == 1) {
            float4 yv = *(const float4*)(g_y + row * 256 + n0 + tx * 4);
            o.x += yv.x; o.y += yv.y; o.z += yv.z; o.w += yv.w;
        }
        ls[0] += o.x; ls[1] += o.y; ls[2] += o.z; ls[3] += o.w;
        ls2[0] += o.x * o.x; ls2[1] += o.y * o.y; ls2[2] += o.z * o.z; ls2[3] += o.w * o.w;
        *(float4*)(out + row * 256 + n0 + tx * 4) = o;
    }

    // ---- BN partials: reduce per-column sums over the CTA's 128 rows ----
    __syncthreads();
    float* red = &As[0][0];            // 2048 floats == 256 threads * 8 slots
#pragma unroll
    for (int i = 0; i < 4; i++) {
        red[tid * 8 + i] = ls[i];
        red[tid * 8 + 4 + i] = ls2[i];
    }
    __syncthreads();
    if (tid < 64) {
        int txr = tid >> 2, ir = tid & 3;
        float s = 0.f, s2 = 0.f;
#pragma unroll
        for (int k = 0; k < 16; k++) {
            s += red[(k * 16 + txr) * 8 + ir];
            s2 += red[(k * 16 + txr) * 8 + 4 + ir];
        }
        int col = n0 + txr * 4 + ir;
        g_part[blockIdx.x * 512 + col] = s;
        g_part[blockIdx.x * 512 + 256 + col] = s2;
    }
}

// ================= mean pool + head =================
__global__ void __launch_bounds__(256) pool1() {
    int b = blockIdx.x >> 3;
    int c = blockIdx.x & 7;
    int e = threadIdx.x;
    const float* p = g_x + ((size_t)b * TLEN + c * 256) * EF + e;
    float s = 0.f;
#pragma unroll 8
    for (int t = 0; t < 256; t++) s += p[(size_t)t * EF];
    g_poolpart[(b * 8 + c) * EF + e] = s;
}

__global__ void __launch_bounds__(256) pool2() {
    int b = blockIdx.x;
    int e = threadIdx.x;
    float s = 0.f;
    for (int c = 0; c < 8; c++) s += g_poolpart[(b * 8 + c) * EF + e];
    g_pool[b * EF + e] = s * (1.0f / (float)TLEN);
}

__global__ void head(const float* __restrict__ Wout, const float* __restrict__ bout,
                     float* __restrict__ out) {
    int tid = threadIdx.x;
    if (tid >= 320) return;
    int b = tid / 10;
    int o = tid % 10;
    float s = bout[o];
    const float* p = g_pool + b * EF;
    for (int e = 0; e < 256; e++) s = fmaf(p[e], Wout[e * 10 + o], s);
    out[b * 10 + o] = s;
}

// ================= host orchestration =================
extern "C" void kernel_launch(void* const* d_in, const int* in_sizes, int n_in,
                              void* d_out, int out_size) {
    const float* x    = (const float*)d_in[0];   // [32,2048,64]
    const float* Wenc = (const float*)d_in[1];   // [64,256]
    const float* benc = (const float*)d_in[2];   // [256]
    const float* nul  = (const float*)d_in[3];   // [6,256]
    const float* thl  = (const float*)d_in[4];   // [6,256]
    const float* Bre  = (const float*)d_in[5];   // [6,256,256]
    const float* Bim  = (const float*)d_in[6];
    const float* Cre  = (const float*)d_in[7];   // [6,256,256]
    const float* Cim  = (const float*)d_in[8];
    const float* Dd   = (const float*)d_in[9];   // [6,256]
    const float* W1   = (const float*)d_in[10];  // [6,256,1024]
    const float* b1   = (const float*)d_in[11];  // [6,1024]
    const float* W2   = (const float*)d_in[12];  // [6,512,256]
    const float* b2   = (const float*)d_in[13];  // [6,256]
    const float* bns  = (const float*)d_in[14];  // [6,256]
    const float* bnb  = (const float*)d_in[15];  // [6,256]
    const float* Wout = (const float*)d_in[16];  // [256,10]
    const float* bout = (const float*)d_in[17];  // [10]

    dim3 g4(512, 4), g8(512, 8);

    // encoder: y = x @ W_enc + b_enc   (writes g_y + BN partials for block 0)
    gemm_nn<0><<<g4, 256>>>(x, 64, Wenc, benc);

    int xsel = 0;  // 0 = read g_y, 1 = read g_x
    for (int i = 0; i < NBLK; i++) {
        bn_stage2<<<1, 256>>>(bns + i * 256, bnb + i * 256);
        lam_kernel<<<1, 256>>>(nul + i * 256, thl + i * 256);
        gemm_bu<<<g4, 256>>>(xsel, Bre + (size_t)i * 65536, 0);
        gemm_bu<<<g4, 256>>>(xsel, Bim + (size_t)i * 65536, 1);
        scan_carry<<<BB * NC, 256>>>();
        scan_prefix<<<BB, 256>>>();
        scan_final<<<BB * NC, 256>>>();
        gemm_cproj<<<g4, 256>>>(Cre + (size_t)i * 65536, Cim + (size_t)i * 65536,
                                Dd + i * 256, xsel);
        gemm_glu<<<g8, 256>>>(W1 + (size_t)i * 256 * 1024, b1 + i * 1024);
        gemm_nn<1><<<g4, 256>>>(nullptr, 512, W2 + (size_t)i * 512 * 256, b2 + i * 256);
        xsel = 1;
    }
    pool1<<<BB * 8, 256>>>();
    pool2<<<BB, 256>>>();
    head<<<1, 320>>>(Wout, bout, (float*)d_out);
}

// round 8
// speedup vs baseline: 1.3922x; 1.0334x over previous
#include <cuda_runtime.h>

// ---------------- problem constants ----------------
#define MTOT 65536      // B*T tokens
#define EF   256        // E features
#define HF   256        // H state size
#define LF   1024       // MLP hidden (pre-GLU)
#define NBLK 6
#define TLEN 2048
#define BB   32
#define NC   32         // scan chunks
#define TC   64         // chunk length (NC*TC == TLEN)

// ---------------- scratch (device globals; no allocation allowed) ----------------
static __device__ float g_y[(size_t)MTOT * EF];      // encoder output / residual anchor
static __device__ float g_x[(size_t)MTOT * EF];      // current block output
static __device__ float g_bure[(size_t)MTOT * HF];
static __device__ float g_buim[(size_t)MTOT * HF];
static __device__ float g_hre[(size_t)MTOT * HF];
static __device__ float g_him[(size_t)MTOT * HF];
static __device__ float g_u[(size_t)MTOT * EF];
static __device__ float g_g[(size_t)MTOT * (LF / 2)];
static __device__ float g_part[512 * 512];           // BN partials: [512 m-blocks][256 sum | 256 sumsq]
static __device__ float g_bna[EF];                   // BN fold: a = rsqrt(var+eps)*scale
static __device__ float g_bnc[EF];                   // BN fold: c = bias - mu*a
static __device__ float g_lr[HF], g_li[HF], g_gam[HF], g_L64r[HF], g_L64i[HF];
static __device__ float g_car_re[BB * NC * HF], g_car_im[BB * NC * HF];
static __device__ float g_pre_re[BB * NC * HF], g_pre_im[BB * NC * HF];
static __device__ float g_poolpart[BB * 8 * EF];
static __device__ float g_pool[BB * EF];

// ================= BN finalize (partials produced by GEMM epilogues) =================
__global__ void __launch_bounds__(256) bn_stage2(const float* __restrict__ scale,
                                                 const float* __restrict__ bias) {
    int e = threadIdx.x;
    float s = 0.f, s2 = 0.f;
    for (int p = 0; p < 512; p++) {
        s += g_part[p * 512 + e];
        s2 += g_part[p * 512 + 256 + e];
    }
    const float inv = 1.0f / 65536.0f;
    float mu = s * inv;
    float var = fmaxf(s2 * inv - mu * mu, 0.0f);
    float a = rsqrtf(var + 1e-5f) * scale[e];
    g_bna[e] = a;
    g_bnc[e] = bias[e] - mu * a;
}

// ================= lambda / gamma precompute =================
__global__ void lam_kernel(const float* __restrict__ nul, const float* __restrict__ thl) {
    int h = threadIdx.x;
    float nu = expf(nul[h]);
    float th = expf(thl[h]);
    float r = expf(-nu);
    float sn, cs;
    sincosf(th, &sn, &cs);
    float lr = r * cs, li = r * sn;
    g_lr[h] = lr;
    g_li[h] = li;
    g_gam[h] = sqrtf(fmaxf(1.0f - r * r, 1e-12f));
    // lam^64 via 6 squarings
    float ar = lr, ai = li;
#pragma unroll
    for (int s = 0; s < 6; s++) {
        float nr = ar * ar - ai * ai;
        float ni = 2.0f * ar * ai;
        ar = nr;
        ai = ni;
    }
    g_L64r[h] = ar;
    g_L64i[h] = ai;
}

// ================= GEMM: (bure,buim) = BN(x) @ [Bre^T, Bim^T] * gamma  (fused dual-B TN) ===
// Shares the BN-folded A tile between the re and im outputs: 1.0 smem-bytes/FMA.
__global__ void __launch_bounds__(256) gemm_bu2(int xsel, const float* __restrict__ Wr,
                                                const float* __restrict__ Wi) {
    const float* A = xsel ? g_x : g_y;
    __shared__ __align__(16) float As[16][128];
    __shared__ __align__(16) float Bsr[16][64];
    __shared__ __align__(16) float Bsi[16][64];
    const int tid = threadIdx.x;
    const int m0 = blockIdx.x * 128;
    const int n0 = blockIdx.y * 64;
    const int tx = tid & 15;
    const int ty = tid >> 4;
    const int lr = tid >> 2;
    const int lk = (tid & 3) * 4;
    float accr[8][4], acci[8][4];
#pragma unroll
    for (int j = 0; j < 8; j++)
#pragma unroll
        for (int i = 0; i < 4; i++) { accr[j][i] = 0.f; acci[j][i] = 0.f; }

    for (int k0 = 0; k0 < 256; k0 += 16) {
        float4 a0 = *(const float4*)(A + (size_t)(m0 + lr) * 256 + k0 + lk);
        float4 a1 = *(const float4*)(A + (size_t)(m0 + lr + 64) * 256 + k0 + lk);
        float4 wr = *(const float4*)(Wr + (size_t)(n0 + lr) * 256 + k0 + lk);
        float4 wi = *(const float4*)(Wi + (size_t)(n0 + lr) * 256 + k0 + lk);
        float4 ba = *(const float4*)(g_bna + k0 + lk);
        float4 bc = *(const float4*)(g_bnc + k0 + lk);
        a0.x = fmaf(ba.x, a0.x, bc.x); a0.y = fmaf(ba.y, a0.y, bc.y);
        a0.z = fmaf(ba.z, a0.z, bc.z); a0.w = fmaf(ba.w, a0.w, bc.w);
        a1.x = fmaf(ba.x, a1.x, bc.x); a1.y = fmaf(ba.y, a1.y, bc.y);
        a1.z = fmaf(ba.z, a1.z, bc.z); a1.w = fmaf(ba.w, a1.w, bc.w);
        __syncthreads();
        As[lk + 0][lr] = a0.x; As[lk + 1][lr] = a0.y; As[lk + 2][lr] = a0.z; As[lk + 3][lr] = a0.w;
        As[lk + 0][lr + 64] = a1.x; As[lk + 1][lr + 64] = a1.y;
        As[lk + 2][lr + 64] = a1.z; As[lk + 3][lr + 64] = a1.w;
        Bsr[lk + 0][lr] = wr.x; Bsr[lk + 1][lr] = wr.y; Bsr[lk + 2][lr] = wr.z; Bsr[lk + 3][lr] = wr.w;
        Bsi[lk + 0][lr] = wi.x; Bsi[lk + 1][lr] = wi.y; Bsi[lk + 2][lr] = wi.z; Bsi[lk + 3][lr] = wi.w;
        __syncthreads();
#pragma unroll
        for (int kk = 0; kk < 16; kk++) {
            float4 av0 = *(const float4*)&As[kk][ty * 8];
            float4 av1 = *(const float4*)&As[kk][ty * 8 + 4];
            float4 br = *(const float4*)&Bsr[kk][tx * 4];
            float4 bi = *(const float4*)&Bsi[kk][tx * 4];
            float a[8] = {av0.x, av0.y, av0.z, av0.w, av1.x, av1.y, av1.z, av1.w};
            float brv[4] = {br.x, br.y, br.z, br.w};
            float biv[4] = {bi.x, bi.y, bi.z, bi.w};
#pragma unroll
            for (int j = 0; j < 8; j++)
#pragma unroll
                for (int i = 0; i < 4; i++) {
                    accr[j][i] = fmaf(a[j], brv[i], accr[j][i]);
                    acci[j][i] = fmaf(a[j], biv[i], acci[j][i]);
                }
        }
    }
    float4 gm = *(const float4*)(g_gam + n0 + tx * 4);
#pragma unroll
    for (int j = 0; j < 8; j++) {
        size_t row = (size_t)(m0 + ty * 8 + j);
        float4 orr, oii;
        orr.x = accr[j][0] * gm.x; orr.y = accr[j][1] * gm.y;
        orr.z = accr[j][2] * gm.z; orr.w = accr[j][3] * gm.w;
        oii.x = acci[j][0] * gm.x; oii.y = acci[j][1] * gm.y;
        oii.z = acci[j][2] * gm.z; oii.w = acci[j][3] * gm.w;
        *(float4*)(g_bure + row * 256 + n0 + tx * 4) = orr;
        *(float4*)(g_buim + row * 256 + n0 + tx * 4) = oii;
    }
}

// ================= chunked scan =================
__global__ void __launch_bounds__(256) scan_carry() {
    int h = threadIdx.x;
    int c = blockIdx.x & 31;
    int b = blockIdx.x >> 5;
    float lr = g_lr[h], li = g_li[h];
    float hr = 0.f, hi = 0.f;
    size_t base = ((size_t)b * TLEN + c * TC) * HF + h;
#pragma unroll 4
    for (int t = 0; t < TC; t++) {
        float ur = g_bure[base + (size_t)t * HF];
        float ui = g_buim[base + (size_t)t * HF];
        float nr = fmaf(lr, hr, fmaf(-li, hi, ur));
        float ni = fmaf(lr, hi, fmaf(li, hr, ui));
        hr = nr;
        hi = ni;
    }
    int ci = (b * NC + c) * HF + h;
    g_car_re[ci] = hr;
    g_car_im[ci] = hi;
}

__global__ void __launch_bounds__(256) scan_prefix() {
    int h = threadIdx.x;
    int b = blockIdx.x;
    float Lr = g_L64r[h], Li = g_L64i[h];
    float Hr = 0.f, Hi = 0.f;
    for (int c = 0; c < NC; c++) {
        int ci = (b * NC + c) * HF + h;
        g_pre_re[ci] = Hr;
        g_pre_im[ci] = Hi;
        float cr = g_car_re[ci], cim = g_car_im[ci];
        float nr = fmaf(Lr, Hr, fmaf(-Li, Hi, cr));
        float ni = fmaf(Lr, Hi, fmaf(Li, Hr, cim));
        Hr = nr;
        Hi = ni;
    }
}

__global__ void __launch_bounds__(256) scan_final() {
    int h = threadIdx.x;
    int c = blockIdx.x & 31;
    int b = blockIdx.x >> 5;
    float lr = g_lr[h], li = g_li[h];
    int ci = (b * NC + c) * HF + h;
    float hr = g_pre_re[ci], hi = g_pre_im[ci];
    size_t base = ((size_t)b * TLEN + c * TC) * HF + h;
#pragma unroll 4
    for (int t = 0; t < TC; t++) {
        size_t idx = base + (size_t)t * HF;
        float ur = g_bure[idx];
        float ui = g_buim[idx];
        float nr = fmaf(lr, hr, fmaf(-li, hi, ur));
        float ni = fmaf(lr, hi, fmaf(li, hr, ui));
        hr = nr;
        hi = ni;
        g_hre[idx] = hr;
        g_him[idx] = hi;
    }
}

// ================= GEMM: u = Re(hs @ Cc) + D*BN(x)  (dual TN) =================
__global__ void __launch_bounds__(256) gemm_cproj(const float* __restrict__ Wr,
                                                  const float* __restrict__ Wi,
                                                  const float* __restrict__ Dv, int xsel) {
    const float* Xin = xsel ? g_x : g_y;
    __shared__ __align__(16) float Asr[16][128];
    __shared__ __align__(16) float Asi[16][128];
    __shared__ __align__(16) float Bsr[16][64];
    __shared__ __align__(16) float Bsi[16][64];
    const int tid = threadIdx.x;
    const int m0 = blockIdx.x * 128;
    const int n0 = blockIdx.y * 64;
    const int tx = tid & 15;
    const int ty = tid >> 4;
    const int lr = tid >> 2;
    const int lk = (tid & 3) * 4;
    float acc[8][4];
#pragma unroll
    for (int j = 0; j < 8; j++)
#pragma unroll
        for (int i = 0; i < 4; i++) acc[j][i] = 0.f;

    for (int k0 = 0; k0 < 256; k0 += 16) {
        float4 ar0 = *(const float4*)(g_hre + (size_t)(m0 + lr) * 256 + k0 + lk);
        float4 ar1 = *(const float4*)(g_hre + (size_t)(m0 + lr + 64) * 256 + k0 + lk);
        float4 ai0 = *(const float4*)(g_him + (size_t)(m0 + lr) * 256 + k0 + lk);
        float4 ai1 = *(const float4*)(g_him + (size_t)(m0 + lr + 64) * 256 + k0 + lk);
        float4 wr = *(const float4*)(Wr + (size_t)(n0 + lr) * 256 + k0 + lk);
        float4 wi = *(const float4*)(Wi + (size_t)(n0 + lr) * 256 + k0 + lk);
        __syncthreads();
        Asr[lk + 0][lr] = ar0.x; Asr[lk + 1][lr] = ar0.y; Asr[lk + 2][lr] = ar0.z; Asr[lk + 3][lr] = ar0.w;
        Asr[lk + 0][lr + 64] = ar1.x; Asr[lk + 1][lr + 64] = ar1.y;
        Asr[lk + 2][lr + 64] = ar1.z; Asr[lk + 3][lr + 64] = ar1.w;
        Asi[lk + 0][lr] = ai0.x; Asi[lk + 1][lr] = ai0.y; Asi[lk + 2][lr] = ai0.z; Asi[lk + 3][lr] = ai0.w;
        Asi[lk + 0][lr + 64] = ai1.x; Asi[lk + 1][lr + 64] = ai1.y;
        Asi[lk + 2][lr + 64] = ai1.z; Asi[lk + 3][lr + 64] = ai1.w;
        Bsr[lk + 0][lr] = wr.x; Bsr[lk + 1][lr] = wr.y; Bsr[lk + 2][lr] = wr.z; Bsr[lk + 3][lr] = wr.w;
        Bsi[lk + 0][lr] = wi.x; Bsi[lk + 1][lr] = wi.y; Bsi[lk + 2][lr] = wi.z; Bsi[lk + 3][lr] = wi.w;
        __syncthreads();
#pragma unroll
        for (int kk = 0; kk < 16; kk++) {
            float4 r0 = *(const float4*)&Asr[kk][ty * 8];
            float4 r1 = *(const float4*)&Asr[kk][ty * 8 + 4];
            float4 i0 = *(const float4*)&Asi[kk][ty * 8];
            float4 i1 = *(const float4*)&Asi[kk][ty * 8 + 4];
            float4 br = *(const float4*)&Bsr[kk][tx * 4];
            float4 bi = *(const float4*)&Bsi[kk][tx * 4];
            float arv[8] = {r0.x, r0.y, r0.z, r0.w, r1.x, r1.y, r1.z, r1.w};
            float aiv[8] = {i0.x, i0.y, i0.z, i0.w, i1.x, i1.y, i1.z, i1.w};
            float brv[4] = {br.x, br.y, br.z, br.w};
            float biv[4] = {bi.x, bi.y, bi.z, bi.w};
#pragma unroll
            for (int j = 0; j < 8; j++)
#pragma unroll
                for (int i = 0; i < 4; i++) {
                    acc[j][i] = fmaf(arv[j], brv[i], acc[j][i]);
                    acc[j][i] = fmaf(-aiv[j], biv[i], acc[j][i]);
                }
        }
    }
    float4 dq = *(const float4*)(Dv + n0 + tx * 4);
    float4 ba = *(const float4*)(g_bna + n0 + tx * 4);
    float4 bc = *(const float4*)(g_bnc + n0 + tx * 4);
#pragma unroll
    for (int j = 0; j < 8; j++) {
        size_t row = (size_t)(m0 + ty * 8 + j);
        float4 xv = *(const float4*)(Xin + row * 256 + n0 + tx * 4);
        float4 o;
        o.x = acc[j][0] + dq.x * fmaf(ba.x, xv.x, bc.x);
        o.y = acc[j][1] + dq.y * fmaf(ba.y, xv.y, bc.y);
        o.z = acc[j][2] + dq.z * fmaf(ba.z, xv.z, bc.z);
        o.w = acc[j][3] + dq.w * fmaf(ba.w, xv.w, bc.w);
        *(float4*)(g_u + row * 256 + n0 + tx * 4) = o;
    }
}

// ================= GEMM: g = GLU(u @ W1 + b1)   (NN, dual-B tile) =================
__global__ void __launch_bounds__(256) gemm_glu(const float* __restrict__ W1,
                                                const float* __restrict__ b1) {
    __shared__ __align__(16) float As[16][128];
    __shared__ __align__(16) float Ba[16][64];
    __shared__ __align__(16) float Bb[16][64];
    const int tid = threadIdx.x;
    const int m0 = blockIdx.x * 128;
    const int n0 = blockIdx.y * 64;  // 0..448 (within 512)
    const int tx = tid & 15;
    const int ty = tid >> 4;
    const int lr = tid >> 2;
    const int lk = (tid & 3) * 4;
    const int bk = tid >> 4;
    const int bn = (tid & 15) * 4;
    float acca[8][4], accb[8][4];
#pragma unroll
    for (int j = 0; j < 8; j++)
#pragma unroll
        for (int i = 0; i < 4; i++) { acca[j][i] = 0.f; accb[j][i] = 0.f; }

    for (int k0 = 0; k0 < 256; k0 += 16) {
        float4 a0 = *(const float4*)(g_u + (size_t)(m0 + lr) * 256 + k0 + lk);
        float4 a1 = *(const float4*)(g_u + (size_t)(m0 + lr + 64) * 256 + k0 + lk);
        float4 wa = *(const float4*)(W1 + (size_t)(k0 + bk) * 1024 + n0 + bn);
        float4 wb = *(const float4*)(W1 + (size_t)(k0 + bk) * 1024 + 512 + n0 + bn);
        __syncthreads();
        As[lk + 0][lr] = a0.x; As[lk + 1][lr] = a0.y; As[lk + 2][lr] = a0.z; As[lk + 3][lr] = a0.w;
        As[lk + 0][lr + 64] = a1.x; As[lk + 1][lr + 64] = a1.y;
        As[lk + 2][lr + 64] = a1.z; As[lk + 3][lr + 64] = a1.w;
        *(float4*)&Ba[bk][bn] = wa;
        *(float4*)&Bb[bk][bn] = wb;
        __syncthreads();
#pragma unroll
        for (int kk = 0; kk < 16; kk++) {
            float4 av0 = *(const float4*)&As[kk][ty * 8];
            float4 av1 = *(const float4*)&As[kk][ty * 8 + 4];
            float4 bva = *(const float4*)&Ba[kk][tx * 4];
            float4 bvb = *(const float4*)&Bb[kk][tx * 4];
            float a[8] = {av0.x, av0.y, av0.z, av0.w, av1.x, av1.y, av1.z, av1.w};
            float ba_[4] = {bva.x, bva.y, bva.z, bva.w};
            float bb_[4] = {bvb.x, bvb.y, bvb.z, bvb.w};
#pragma unroll
            for (int j = 0; j < 8; j++)
#pragma unroll
                for (int i = 0; i < 4; i++) {
                    acca[j][i] = fmaf(a[j], ba_[i], acca[j][i]);
                    accb[j][i] = fmaf(a[j], bb_[i], accb[j][i]);
                }
        }
    }
    float4 b1a = *(const float4*)(b1 + n0 + tx * 4);
    float4 b1b = *(const float4*)(b1 + 512 + n0 + tx * 4);
#pragma unroll
    for (int j = 0; j < 8; j++) {
        float za[4], zb[4];
        za[0] = acca[j][0] + b1a.x; za[1] = acca[j][1] + b1a.y;
        za[2] = acca[j][2] + b1a.z; za[3] = acca[j][3] + b1a.w;
        zb[0] = accb[j][0] + b1b.x; zb[1] = accb[j][1] + b1b.y;
        zb[2] = accb[j][2] + b1b.z; zb[3] = accb[j][3] + b1b.w;
        float4 o;
        o.x = __fdividef(za[0], 1.0f + __expf(-zb[0]));
        o.y = __fdividef(za[1], 1.0f + __expf(-zb[1]));
        o.z = __fdividef(za[2], 1.0f + __expf(-zb[2]));
        o.w = __fdividef(za[3], 1.0f + __expf(-zb[3]));
        *(float4*)(g_g + (size_t)(m0 + ty * 8 + j) * 512 + n0 + tx * 4) = o;
    }
}

// ================= GEMM NN (encoder: ROLE=0, MLP2+residual: ROLE=1) =================
// ROLE 0: out(g_y) = A_ext[M,K] @ B[K,256] + bias          (K=64)
// ROLE 1: out(g_x) = g_g[M,512] @ B[512,256] + bias + g_y  (K=512)
// Both epilogues also emit per-CTA BN partial sums (sum, sumsq) into g_part.
template <int ROLE>
__global__ void __launch_bounds__(256) gemm_nn(const float* __restrict__ Aext, int K,
                                               const float* __restrict__ B,
                                               const float* __restrict__ bias) {
    const float* A = (ROLE == 0) ? Aext : g_g;
    float* out = (ROLE == 0) ? g_y : g_x;
    __shared__ __align__(16) float As[16][128];
    __shared__ __align__(16) float Bs[16][64];
    const int tid = threadIdx.x;
    const int m0 = blockIdx.x * 128;
    const int n0 = blockIdx.y * 64;
    const int tx = tid & 15;
    const int ty = tid >> 4;
    const int lr = tid >> 2;
    const int lk = (tid & 3) * 4;
    const int bk = tid >> 4;
    const int bn = (tid & 15) * 4;
    float acc[8][4];
#pragma unroll
    for (int j = 0; j < 8; j++)
#pragma unroll
        for (int i = 0; i < 4; i++) acc[j][i] = 0.f;

    for (int k0 = 0; k0 < K; k0 += 16) {
        float4 a0 = *(const float4*)(A + (size_t)(m0 + lr) * K + k0 + lk);
        float4 a1 = *(const float4*)(A + (size_t)(m0 + lr + 64) * K + k0 + lk);
        float4 wv = *(const float4*)(B + (size_t)(k0 + bk) * 256 + n0 + bn);
        __syncthreads();
        As[lk + 0][lr] = a0.x; As[lk + 1][lr] = a0.y; As[lk + 2][lr] = a0.z; As[lk + 3][lr] = a0.w;
        As[lk + 0][lr + 64] = a1.x; As[lk + 1][lr + 64] = a1.y;
        As[lk + 2][lr + 64] = a1.z; As[lk + 3][lr + 64] = a1.w;
        *(float4*)&Bs[bk][bn] = wv;
        __syncthreads();
#pragma unroll
        for (int kk = 0; kk < 16; kk++) {
            float4 av0 = *(const float4*)&As[kk][ty * 8];
            float4 av1 = *(const float4*)&As[kk][ty * 8 + 4];
            float4 bv = *(const float4*)&Bs[kk][tx * 4];
            float a[8] = {av0.x, av0.y, av0.z, av0.w, av1.x, av1.y, av1.z, av1.w};
            float b[4] = {bv.x, bv.y, bv.z, bv.w};
#pragma unroll
            for (int j = 0; j < 8; j++)
#pragma unroll
                for (int i = 0; i < 4; i++) acc[j][i] = fmaf(a[j], b[i], acc[j][i]);
        }
    }
    float4 bq = *(const float4*)(bias + n0 + tx * 4);
    float ls[4] = {0.f, 0.f, 0.f, 0.f};
    float ls2[4] = {0.f, 0.f, 0.f, 0.f};
#pragma unroll
    for (int j = 0; j < 8; j++) {
        size_t row = (size_t)(m0 + ty * 8 + j);
        float4 o;
        o.x = acc[j][0] + bq.x; o.y = acc[j][1] + bq.y;
        o.z = acc[j][2] + bq.z; o.w = acc[j][3] + bq.w;
        if (ROLE == 1) {
            float4 yv = *(const float4*)(g_y + row * 256 + n0 + tx * 4);
            o.x += yv.x; o.y += yv.y; o.z += yv.z; o.w += yv.w;
        }
        ls[0] += o.x; ls[1] += o.y; ls[2] += o.z; ls[3] += o.w;
        ls2[0] += o.x * o.x; ls2[1] += o.y * o.y; ls2[2] += o.z * o.z; ls2[3] += o.w * o.w;
        *(float4*)(out + row * 256 + n0 + tx * 4) = o;
    }

    // ---- BN partials: reduce per-column sums over the CTA's 128 rows ----
    __syncthreads();
    float* red = &As[0][0];            // 2048 floats == 256 threads * 8 slots
#pragma unroll
    for (int i = 0; i < 4; i++) {
        red[tid * 8 + i] = ls[i];
        red[tid * 8 + 4 + i] = ls2[i];
    }
    __syncthreads();
    if (tid < 64) {
        int txr = tid >> 2, ir = tid & 3;
        float s = 0.f, s2 = 0.f;
#pragma unroll
        for (int k = 0; k < 16; k++) {
            s += red[(k * 16 + txr) * 8 + ir];
            s2 += red[(k * 16 + txr) * 8 + 4 + ir];
        }
        int col = n0 + txr * 4 + ir;
        g_part[blockIdx.x * 512 + col] = s;
        g_part[blockIdx.x * 512 + 256 + col] = s2;
    }
}

// ================= mean pool + head =================
__global__ void __launch_bounds__(256) pool1() {
    int b = blockIdx.x >> 3;
    int c = blockIdx.x & 7;
    int e = threadIdx.x;
    const float* p = g_x + ((size_t)b * TLEN + c * 256) * EF + e;
    float s = 0.f;
#pragma unroll 8
    for (int t = 0; t < 256; t++) s += p[(size_t)t * EF];
    g_poolpart[(b * 8 + c) * EF + e] = s;
}

__global__ void __launch_bounds__(256) pool2() {
    int b = blockIdx.x;
    int e = threadIdx.x;
    float s = 0.f;
    for (int c = 0; c < 8; c++) s += g_poolpart[(b * 8 + c) * EF + e];
    g_pool[b * EF + e] = s * (1.0f / (float)TLEN);
}

__global__ void head(const float* __restrict__ Wout, const float* __restrict__ bout,
                     float* __restrict__ out) {
    int tid = threadIdx.x;
    if (tid >= 320) return;
    int b = tid / 10;
    int o = tid % 10;
    float s = bout[o];
    const float* p = g_pool + b * EF;
    for (int e = 0; e < 256; e++) s = fmaf(p[e], Wout[e * 10 + o], s);
    out[b * 10 + o] = s;
}

// ================= host orchestration =================
extern "C" void kernel_launch(void* const* d_in, const int* in_sizes, int n_in,
                              void* d_out, int out_size) {
    const float* x    = (const float*)d_in[0];   // [32,2048,64]
    const float* Wenc = (const float*)d_in[1];   // [64,256]
    const float* benc = (const float*)d_in[2];   // [256]
    const float* nul  = (const float*)d_in[3];   // [6,256]
    const float* thl  = (const float*)d_in[4];   // [6,256]
    const float* Bre  = (const float*)d_in[5];   // [6,256,256]
    const float* Bim  = (const float*)d_in[6];
    const float* Cre  = (const float*)d_in[7];   // [6,256,256]
    const float* Cim  = (const float*)d_in[8];
    const float* Dd   = (const float*)d_in[9];   // [6,256]
    const float* W1   = (const float*)d_in[10];  // [6,256,1024]
    const float* b1   = (const float*)d_in[11];  // [6,1024]
    const float* W2   = (const float*)d_in[12];  // [6,512,256]
    const float* b2   = (const float*)d_in[13];  // [6,256]
    const float* bns  = (const float*)d_in[14];  // [6,256]
    const float* bnb  = (const float*)d_in[15];  // [6,256]
    const float* Wout = (const float*)d_in[16];  // [256,10]
    const float* bout = (const float*)d_in[17];  // [10]

    dim3 g4(512, 4), g8(512, 8);

    // encoder: y = x @ W_enc + b_enc   (writes g_y + BN partials)
    gemm_nn<0><<<g4, 256>>>(x, 64, Wenc, benc);

    int xsel = 0;  // 0 = read g_y, 1 = read g_x
    for (int i = 0; i < NBLK; i++) {
        bn_stage2<<<1, 256>>>(bns + i * 256, bnb + i * 256);
        lam_kernel<<<1, 256>>>(nul + i * 256, thl + i * 256);
        gemm_bu2<<<g4, 256>>>(xsel, Bre + (size_t)i * 65536, Bim + (size_t)i * 65536);
        scan_carry<<<BB * NC, 256>>>();
        scan_prefix<<<BB, 256>>>();
        scan_final<<<BB * NC, 256>>>();
        gemm_cproj<<<g4, 256>>>(Cre + (size_t)i * 65536, Cim + (size_t)i * 65536,
                                Dd + i * 256, xsel);
        gemm_glu<<<g8, 256>>>(W1 + (size_t)i * 256 * 1024, b1 + i * 1024);
        gemm_nn<1><<<g4, 256>>>(nullptr, 512, W2 + (size_t)i * 512 * 256, b2 + i * 256);
        xsel = 1;
    }
    pool1<<<BB * 8, 256>>>();
    pool2<<<BB, 256>>>();
    head<<<1, 320>>>(Wout, bout, (float*)d_out);
}

// round 9
// speedup vs baseline: 1.4828x; 1.0651x over previous
#include <cuda_runtime.h>

// ---------------- problem constants ----------------
#define MTOT 65536      // B*T tokens
#define EF   256        // E features
#define HF   256        // H state size
#define LF   1024       // MLP hidden (pre-GLU)
#define NBLK 6
#define TLEN 2048
#define BB   32
#define NC   32         // scan chunks
#define TC   64         // chunk length (NC*TC == TLEN)

// ---------------- scratch (device globals; no allocation allowed) ----------------
static __device__ float g_y[(size_t)MTOT * EF];      // encoder output / residual anchor
static __device__ float g_x[(size_t)MTOT * EF];      // current block output
static __device__ float g_bure[(size_t)MTOT * HF];
static __device__ float g_buim[(size_t)MTOT * HF];
static __device__ float g_hre[(size_t)MTOT * HF];
static __device__ float g_him[(size_t)MTOT * HF];
static __device__ float g_u[(size_t)MTOT * EF];
static __device__ float g_g[(size_t)MTOT * (LF / 2)];
static __device__ float g_part[512 * 512];           // BN partials: [512 m-blocks][256 sum | 256 sumsq]
static __device__ float g_bna[EF];                   // BN fold: a = rsqrt(var+eps)*scale
static __device__ float g_bnc[EF];                   // BN fold: c = bias - mu*a
static __device__ float g_lr[HF], g_li[HF], g_gam[HF], g_L64r[HF], g_L64i[HF];
static __device__ float g_car_re[BB * NC * HF], g_car_im[BB * NC * HF];
static __device__ float g_pre_re[BB * NC * HF], g_pre_im[BB * NC * HF];
static __device__ float g_poolpart[BB * 8 * EF];
static __device__ float g_pool[BB * EF];

// ================= BN finalize (partials produced by GEMM epilogues) =================
__global__ void __launch_bounds__(256) bn_stage2(const float* __restrict__ scale,
                                                 const float* __restrict__ bias) {
    int e = threadIdx.x;
    float s = 0.f, s2 = 0.f;
    for (int p = 0; p < 512; p++) {
        s += g_part[p * 512 + e];
        s2 += g_part[p * 512 + 256 + e];
    }
    const float inv = 1.0f / 65536.0f;
    float mu = s * inv;
    float var = fmaxf(s2 * inv - mu * mu, 0.0f);
    float a = rsqrtf(var + 1e-5f) * scale[e];
    g_bna[e] = a;
    g_bnc[e] = bias[e] - mu * a;
}

// ================= lambda / gamma precompute =================
__global__ void lam_kernel(const float* __restrict__ nul, const float* __restrict__ thl) {
    int h = threadIdx.x;
    float nu = expf(nul[h]);
    float th = expf(thl[h]);
    float r = expf(-nu);
    float sn, cs;
    sincosf(th, &sn, &cs);
    float lr = r * cs, li = r * sn;
    g_lr[h] = lr;
    g_li[h] = li;
    g_gam[h] = sqrtf(fmaxf(1.0f - r * r, 1e-12f));
    float ar = lr, ai = li;
#pragma unroll
    for (int s = 0; s < 6; s++) {
        float nr = ar * ar - ai * ai;
        float ni = 2.0f * ar * ai;
        ar = nr;
        ai = ni;
    }
    g_L64r[h] = ar;
    g_L64i[h] = ai;
}

// ================= GEMM: (bure,buim) = BN(x) @ [Bre^T, Bim^T] * gamma  (fused dual-B TN) ===
__global__ void __launch_bounds__(256) gemm_bu2(int xsel, const float* __restrict__ Wr,
                                                const float* __restrict__ Wi) {
    const float* A = xsel ? g_x : g_y;
    __shared__ __align__(16) float As[16][128];
    __shared__ __align__(16) float Bsr[16][64];
    __shared__ __align__(16) float Bsi[16][64];
    const int tid = threadIdx.x;
    const int m0 = blockIdx.x * 128;
    const int n0 = blockIdx.y * 64;
    const int tx = tid & 15;
    const int ty = tid >> 4;
    const int lr = tid >> 2;
    const int lk = (tid & 3) * 4;
    float accr[8][4], acci[8][4];
#pragma unroll
    for (int j = 0; j < 8; j++)
#pragma unroll
        for (int i = 0; i < 4; i++) { accr[j][i] = 0.f; acci[j][i] = 0.f; }

    for (int k0 = 0; k0 < 256; k0 += 16) {
        float4 a0 = *(const float4*)(A + (size_t)(m0 + lr) * 256 + k0 + lk);
        float4 a1 = *(const float4*)(A + (size_t)(m0 + lr + 64) * 256 + k0 + lk);
        float4 wr = *(const float4*)(Wr + (size_t)(n0 + lr) * 256 + k0 + lk);
        float4 wi = *(const float4*)(Wi + (size_t)(n0 + lr) * 256 + k0 + lk);
        float4 ba = *(const float4*)(g_bna + k0 + lk);
        float4 bc = *(const float4*)(g_bnc + k0 + lk);
        a0.x = fmaf(ba.x, a0.x, bc.x); a0.y = fmaf(ba.y, a0.y, bc.y);
        a0.z = fmaf(ba.z, a0.z, bc.z); a0.w = fmaf(ba.w, a0.w, bc.w);
        a1.x = fmaf(ba.x, a1.x, bc.x); a1.y = fmaf(ba.y, a1.y, bc.y);
        a1.z = fmaf(ba.z, a1.z, bc.z); a1.w = fmaf(ba.w, a1.w, bc.w);
        __syncthreads();
        As[lk + 0][lr] = a0.x; As[lk + 1][lr] = a0.y; As[lk + 2][lr] = a0.z; As[lk + 3][lr] = a0.w;
        As[lk + 0][lr + 64] = a1.x; As[lk + 1][lr + 64] = a1.y;
        As[lk + 2][lr + 64] = a1.z; As[lk + 3][lr + 64] = a1.w;
        Bsr[lk + 0][lr] = wr.x; Bsr[lk + 1][lr] = wr.y; Bsr[lk + 2][lr] = wr.z; Bsr[lk + 3][lr] = wr.w;
        Bsi[lk + 0][lr] = wi.x; Bsi[lk + 1][lr] = wi.y; Bsi[lk + 2][lr] = wi.z; Bsi[lk + 3][lr] = wi.w;
        __syncthreads();
#pragma unroll
        for (int kk = 0; kk < 16; kk++) {
            float4 av0 = *(const float4*)&As[kk][ty * 8];
            float4 av1 = *(const float4*)&As[kk][ty * 8 + 4];
            float4 br = *(const float4*)&Bsr[kk][tx * 4];
            float4 bi = *(const float4*)&Bsi[kk][tx * 4];
            float a[8] = {av0.x, av0.y, av0.z, av0.w, av1.x, av1.y, av1.z, av1.w};
            float brv[4] = {br.x, br.y, br.z, br.w};
            float biv[4] = {bi.x, bi.y, bi.z, bi.w};
#pragma unroll
            for (int j = 0; j < 8; j++)
#pragma unroll
                for (int i = 0; i < 4; i++) {
                    accr[j][i] = fmaf(a[j], brv[i], accr[j][i]);
                    acci[j][i] = fmaf(a[j], biv[i], acci[j][i]);
                }
        }
    }
    float4 gm = *(const float4*)(g_gam + n0 + tx * 4);
#pragma unroll
    for (int j = 0; j < 8; j++) {
        size_t row = (size_t)(m0 + ty * 8 + j);
        float4 orr, oii;
        orr.x = accr[j][0] * gm.x; orr.y = accr[j][1] * gm.y;
        orr.z = accr[j][2] * gm.z; orr.w = accr[j][3] * gm.w;
        oii.x = acci[j][0] * gm.x; oii.y = acci[j][1] * gm.y;
        oii.z = acci[j][2] * gm.z; oii.w = acci[j][3] * gm.w;
        *(float4*)(g_bure + row * 256 + n0 + tx * 4) = orr;
        *(float4*)(g_buim + row * 256 + n0 + tx * 4) = oii;
    }
}

// ================= chunked scan =================
__global__ void __launch_bounds__(256) scan_carry() {
    int h = threadIdx.x;
    int c = blockIdx.x & 31;
    int b = blockIdx.x >> 5;
    float lr = g_lr[h], li = g_li[h];
    float hr = 0.f, hi = 0.f;
    size_t base = ((size_t)b * TLEN + c * TC) * HF + h;
#pragma unroll 4
    for (int t = 0; t < TC; t++) {
        float ur = g_bure[base + (size_t)t * HF];
        float ui = g_buim[base + (size_t)t * HF];
        float nr = fmaf(lr, hr, fmaf(-li, hi, ur));
        float ni = fmaf(lr, hi, fmaf(li, hr, ui));
        hr = nr;
        hi = ni;
    }
    int ci = (b * NC + c) * HF + h;
    g_car_re[ci] = hr;
    g_car_im[ci] = hi;
}

__global__ void __launch_bounds__(256) scan_prefix() {
    int h = threadIdx.x;
    int b = blockIdx.x;
    float Lr = g_L64r[h], Li = g_L64i[h];
    float Hr = 0.f, Hi = 0.f;
    for (int c = 0; c < NC; c++) {
        int ci = (b * NC + c) * HF + h;
        g_pre_re[ci] = Hr;
        g_pre_im[ci] = Hi;
        float cr = g_car_re[ci], cim = g_car_im[ci];
        float nr = fmaf(Lr, Hr, fmaf(-Li, Hi, cr));
        float ni = fmaf(Lr, Hi, fmaf(Li, Hr, cim));
        Hr = nr;
        Hi = ni;
    }
}

__global__ void __launch_bounds__(256) scan_final() {
    int h = threadIdx.x;
    int c = blockIdx.x & 31;
    int b = blockIdx.x >> 5;
    float lr = g_lr[h], li = g_li[h];
    int ci = (b * NC + c) * HF + h;
    float hr = g_pre_re[ci], hi = g_pre_im[ci];
    size_t base = ((size_t)b * TLEN + c * TC) * HF + h;
#pragma unroll 4
    for (int t = 0; t < TC; t++) {
        size_t idx = base + (size_t)t * HF;
        float ur = g_bure[idx];
        float ui = g_buim[idx];
        float nr = fmaf(lr, hr, fmaf(-li, hi, ur));
        float ni = fmaf(lr, hi, fmaf(li, hr, ui));
        hr = nr;
        hi = ni;
        g_hre[idx] = hr;
        g_him[idx] = hi;
    }
}

// ================= GEMM: u = Re(hs @ Cc) + D*BN(x)  (dual TN, wide N=128) =================
// Thread tile: 8 rows x 8 cols (col groups tx*4 and 64+tx*4). 1.0 smem-B/FMA.
__global__ void __launch_bounds__(256) gemm_cproj(const float* __restrict__ Wr,
                                                  const float* __restrict__ Wi,
                                                  const float* __restrict__ Dv, int xsel) {
    const float* Xin = xsel ? g_x : g_y;
    __shared__ __align__(16) float Asr[16][128];
    __shared__ __align__(16) float Asi[16][128];
    __shared__ __align__(16) float Bsr[16][128];
    __shared__ __align__(16) float Bsi[16][128];
    const int tid = threadIdx.x;
    const int m0 = blockIdx.x * 128;
    const int n0 = blockIdx.y * 128;
    const int tx = tid & 15;
    const int ty = tid >> 4;
    const int lr = tid >> 2;
    const int lk = (tid & 3) * 4;
    float acc[8][2][4];
#pragma unroll
    for (int j = 0; j < 8; j++)
#pragma unroll
        for (int g = 0; g < 2; g++)
#pragma unroll
            for (int i = 0; i < 4; i++) acc[j][g][i] = 0.f;

    for (int k0 = 0; k0 < 256; k0 += 16) {
        float4 ar0 = *(const float4*)(g_hre + (size_t)(m0 + lr) * 256 + k0 + lk);
        float4 ar1 = *(const float4*)(g_hre + (size_t)(m0 + lr + 64) * 256 + k0 + lk);
        float4 ai0 = *(const float4*)(g_him + (size_t)(m0 + lr) * 256 + k0 + lk);
        float4 ai1 = *(const float4*)(g_him + (size_t)(m0 + lr + 64) * 256 + k0 + lk);
        float4 wr0 = *(const float4*)(Wr + (size_t)(n0 + lr) * 256 + k0 + lk);
        float4 wr1 = *(const float4*)(Wr + (size_t)(n0 + lr + 64) * 256 + k0 + lk);
        float4 wi0 = *(const float4*)(Wi + (size_t)(n0 + lr) * 256 + k0 + lk);
        float4 wi1 = *(const float4*)(Wi + (size_t)(n0 + lr + 64) * 256 + k0 + lk);
        __syncthreads();
        Asr[lk + 0][lr] = ar0.x; Asr[lk + 1][lr] = ar0.y; Asr[lk + 2][lr] = ar0.z; Asr[lk + 3][lr] = ar0.w;
        Asr[lk + 0][lr + 64] = ar1.x; Asr[lk + 1][lr + 64] = ar1.y;
        Asr[lk + 2][lr + 64] = ar1.z; Asr[lk + 3][lr + 64] = ar1.w;
        Asi[lk + 0][lr] = ai0.x; Asi[lk + 1][lr] = ai0.y; Asi[lk + 2][lr] = ai0.z; Asi[lk + 3][lr] = ai0.w;
        Asi[lk + 0][lr + 64] = ai1.x; Asi[lk + 1][lr + 64] = ai1.y;
        Asi[lk + 2][lr + 64] = ai1.z; Asi[lk + 3][lr + 64] = ai1.w;
        Bsr[lk + 0][lr] = wr0.x; Bsr[lk + 1][lr] = wr0.y; Bsr[lk + 2][lr] = wr0.z; Bsr[lk + 3][lr] = wr0.w;
        Bsr[lk + 0][lr + 64] = wr1.x; Bsr[lk + 1][lr + 64] = wr1.y;
        Bsr[lk + 2][lr + 64] = wr1.z; Bsr[lk + 3][lr + 64] = wr1.w;
        Bsi[lk + 0][lr] = wi0.x; Bsi[lk + 1][lr] = wi0.y; Bsi[lk + 2][lr] = wi0.z; Bsi[lk + 3][lr] = wi0.w;
        Bsi[lk + 0][lr + 64] = wi1.x; Bsi[lk + 1][lr + 64] = wi1.y;
        Bsi[lk + 2][lr + 64] = wi1.z; Bsi[lk + 3][lr + 64] = wi1.w;
        __syncthreads();
#pragma unroll
        for (int kk = 0; kk < 16; kk++) {
            float4 r0 = *(const float4*)&Asr[kk][ty * 8];
            float4 r1 = *(const float4*)&Asr[kk][ty * 8 + 4];
            float4 i0 = *(const float4*)&Asi[kk][ty * 8];
            float4 i1 = *(const float4*)&Asi[kk][ty * 8 + 4];
            float4 br0 = *(const float4*)&Bsr[kk][tx * 4];
            float4 br1 = *(const float4*)&Bsr[kk][tx * 4 + 64];
            float4 bi0 = *(const float4*)&Bsi[kk][tx * 4];
            float4 bi1 = *(const float4*)&Bsi[kk][tx * 4 + 64];
            float arv[8] = {r0.x, r0.y, r0.z, r0.w, r1.x, r1.y, r1.z, r1.w};
            float aiv[8] = {i0.x, i0.y, i0.z, i0.w, i1.x, i1.y, i1.z, i1.w};
            float brv[2][4] = {{br0.x, br0.y, br0.z, br0.w}, {br1.x, br1.y, br1.z, br1.w}};
            float biv[2][4] = {{bi0.x, bi0.y, bi0.z, bi0.w}, {bi1.x, bi1.y, bi1.z, bi1.w}};
#pragma unroll
            for (int j = 0; j < 8; j++)
#pragma unroll
                for (int g = 0; g < 2; g++)
#pragma unroll
                    for (int i = 0; i < 4; i++) {
                        acc[j][g][i] = fmaf(arv[j], brv[g][i], acc[j][g][i]);
                        acc[j][g][i] = fmaf(-aiv[j], biv[g][i], acc[j][g][i]);
                    }
        }
    }
#pragma unroll
    for (int g = 0; g < 2; g++) {
        int n = n0 + g * 64 + tx * 4;
        float4 dq = *(const float4*)(Dv + n);
        float4 ba = *(const float4*)(g_bna + n);
        float4 bc = *(const float4*)(g_bnc + n);
#pragma unroll
        for (int j = 0; j < 8; j++) {
            size_t row = (size_t)(m0 + ty * 8 + j);
            float4 xv = *(const float4*)(Xin + row * 256 + n);
            float4 o;
            o.x = acc[j][g][0] + dq.x * fmaf(ba.x, xv.x, bc.x);
            o.y = acc[j][g][1] + dq.y * fmaf(ba.y, xv.y, bc.y);
            o.z = acc[j][g][2] + dq.z * fmaf(ba.z, xv.z, bc.z);
            o.w = acc[j][g][3] + dq.w * fmaf(ba.w, xv.w, bc.w);
            *(float4*)(g_u + row * 256 + n) = o;
        }
    }
}

// ================= GEMM: g = GLU(u @ W1 + b1)   (NN, dual-B tile) =================
__global__ void __launch_bounds__(256) gemm_glu(const float* __restrict__ W1,
                                                const float* __restrict__ b1) {
    __shared__ __align__(16) float As[16][128];
    __shared__ __align__(16) float Ba[16][64];
    __shared__ __align__(16) float Bb[16][64];
    const int tid = threadIdx.x;
    const int m0 = blockIdx.x * 128;
    const int n0 = blockIdx.y * 64;  // 0..448 (within 512)
    const int tx = tid & 15;
    const int ty = tid >> 4;
    const int lr = tid >> 2;
    const int lk = (tid & 3) * 4;
    const int bk = tid >> 4;
    const int bn = (tid & 15) * 4;
    float acca[8][4], accb[8][4];
#pragma unroll
    for (int j = 0; j < 8; j++)
#pragma unroll
        for (int i = 0; i < 4; i++) { acca[j][i] = 0.f; accb[j][i] = 0.f; }

    for (int k0 = 0; k0 < 256; k0 += 16) {
        float4 a0 = *(const float4*)(g_u + (size_t)(m0 + lr) * 256 + k0 + lk);
        float4 a1 = *(const float4*)(g_u + (size_t)(m0 + lr + 64) * 256 + k0 + lk);
        float4 wa = *(const float4*)(W1 + (size_t)(k0 + bk) * 1024 + n0 + bn);
        float4 wb = *(const float4*)(W1 + (size_t)(k0 + bk) * 1024 + 512 + n0 + bn);
        __syncthreads();
        As[lk + 0][lr] = a0.x; As[lk + 1][lr] = a0.y; As[lk + 2][lr] = a0.z; As[lk + 3][lr] = a0.w;
        As[lk + 0][lr + 64] = a1.x; As[lk + 1][lr + 64] = a1.y;
        As[lk + 2][lr + 64] = a1.z; As[lk + 3][lr + 64] = a1.w;
        *(float4*)&Ba[bk][bn] = wa;
        *(float4*)&Bb[bk][bn] = wb;
        __syncthreads();
#pragma unroll
        for (int kk = 0; kk < 16; kk++) {
            float4 av0 = *(const float4*)&As[kk][ty * 8];
            float4 av1 = *(const float4*)&As[kk][ty * 8 + 4];
            float4 bva = *(const float4*)&Ba[kk][tx * 4];
            float4 bvb = *(const float4*)&Bb[kk][tx * 4];
            float a[8] = {av0.x, av0.y, av0.z, av0.w, av1.x, av1.y, av1.z, av1.w};
            float ba_[4] = {bva.x, bva.y, bva.z, bva.w};
            float bb_[4] = {bvb.x, bvb.y, bvb.z, bvb.w};
#pragma unroll
            for (int j = 0; j < 8; j++)
#pragma unroll
                for (int i = 0; i < 4; i++) {
                    acca[j][i] = fmaf(a[j], ba_[i], acca[j][i]);
                    accb[j][i] = fmaf(a[j], bb_[i], accb[j][i]);
                }
        }
    }
    float4 b1a = *(const float4*)(b1 + n0 + tx * 4);
    float4 b1b = *(const float4*)(b1 + 512 + n0 + tx * 4);
#pragma unroll
    for (int j = 0; j < 8; j++) {
        float za[4], zb[4];
        za[0] = acca[j][0] + b1a.x; za[1] = acca[j][1] + b1a.y;
        za[2] = acca[j][2] + b1a.z; za[3] = acca[j][3] + b1a.w;
        zb[0] = accb[j][0] + b1b.x; zb[1] = accb[j][1] + b1b.y;
        zb[2] = accb[j][2] + b1b.z; zb[3] = accb[j][3] + b1b.w;
        float4 o;
        o.x = __fdividef(za[0], 1.0f + __expf(-zb[0]));
        o.y = __fdividef(za[1], 1.0f + __expf(-zb[1]));
        o.z = __fdividef(za[2], 1.0f + __expf(-zb[2]));
        o.w = __fdividef(za[3], 1.0f + __expf(-zb[3]));
        *(float4*)(g_g + (size_t)(m0 + ty * 8 + j) * 512 + n0 + tx * 4) = o;
    }
}

// ================= GEMM NN wide (encoder ROLE=0, MLP2+residual ROLE=1; N-tile 128) =======
// Thread tile 8 rows x 8 cols (groups tx*4 and 64+tx*4). Emits BN partials.
template <int ROLE>
__global__ void __launch_bounds__(256) gemm_nn(const float* __restrict__ Aext, int K,
                                               const float* __restrict__ B,
                                               const float* __restrict__ bias) {
    const float* A = (ROLE == 0) ? Aext : g_g;
    float* out = (ROLE == 0) ? g_y : g_x;
    __shared__ __align__(16) float As[16][128];
    __shared__ __align__(16) float Bs[16][128];
    const int tid = threadIdx.x;
    const int m0 = blockIdx.x * 128;
    const int n0 = blockIdx.y * 128;
    const int tx = tid & 15;
    const int ty = tid >> 4;
    const int lr = tid >> 2;
    const int lk = (tid & 3) * 4;
    const int bk = tid >> 4;
    const int bn = (tid & 15) * 4;
    float acc[8][2][4];
#pragma unroll
    for (int j = 0; j < 8; j++)
#pragma unroll
        for (int g = 0; g < 2; g++)
#pragma unroll
            for (int i = 0; i < 4; i++) acc[j][g][i] = 0.f;

    for (int k0 = 0; k0 < K; k0 += 16) {
        float4 a0 = *(const float4*)(A + (size_t)(m0 + lr) * K + k0 + lk);
        float4 a1 = *(const float4*)(A + (size_t)(m0 + lr + 64) * K + k0 + lk);
        float4 wv0 = *(const float4*)(B + (size_t)(k0 + bk) * 256 + n0 + bn);
        float4 wv1 = *(const float4*)(B + (size_t)(k0 + bk) * 256 + n0 + 64 + bn);
        __syncthreads();
        As[lk + 0][lr] = a0.x; As[lk + 1][lr] = a0.y; As[lk + 2][lr] = a0.z; As[lk + 3][lr] = a0.w;
        As[lk + 0][lr + 64] = a1.x; As[lk + 1][lr + 64] = a1.y;
        As[lk + 2][lr + 64] = a1.z; As[lk + 3][lr + 64] = a1.w;
        *(float4*)&Bs[bk][bn] = wv0;
        *(float4*)&Bs[bk][bn + 64] = wv1;
        __syncthreads();
#pragma unroll
        for (int kk = 0; kk < 16; kk++) {
            float4 av0 = *(const float4*)&As[kk][ty * 8];
            float4 av1 = *(const float4*)&As[kk][ty * 8 + 4];
            float4 bv0 = *(const float4*)&Bs[kk][tx * 4];
            float4 bv1 = *(const float4*)&Bs[kk][tx * 4 + 64];
            float a[8] = {av0.x, av0.y, av0.z, av0.w, av1.x, av1.y, av1.z, av1.w};
            float bv[2][4] = {{bv0.x, bv0.y, bv0.z, bv0.w}, {bv1.x, bv1.y, bv1.z, bv1.w}};
#pragma unroll
            for (int j = 0; j < 8; j++)
#pragma unroll
                for (int g = 0; g < 2; g++)
#pragma unroll
                    for (int i = 0; i < 4; i++)
                        acc[j][g][i] = fmaf(a[j], bv[g][i], acc[j][g][i]);
        }
    }

    float ls[2][4], ls2[2][4];
#pragma unroll
    for (int g = 0; g < 2; g++)
#pragma unroll
        for (int i = 0; i < 4; i++) { ls[g][i] = 0.f; ls2[g][i] = 0.f; }
#pragma unroll
    for (int g = 0; g < 2; g++) {
        int n = n0 + g * 64 + tx * 4;
        float4 bq = *(const float4*)(bias + n);
#pragma unroll
        for (int j = 0; j < 8; j++) {
            size_t row = (size_t)(m0 + ty * 8 + j);
            float4 o;
            o.x = acc[j][g][0] + bq.x; o.y = acc[j][g][1] + bq.y;
            o.z = acc[j][g][2] + bq.z; o.w = acc[j][g][3] + bq.w;
            if (ROLE == 1) {
                float4 yv = *(const float4*)(g_y + row * 256 + n);
                o.x += yv.x; o.y += yv.y; o.z += yv.z; o.w += yv.w;
            }
            ls[g][0] += o.x; ls[g][1] += o.y; ls[g][2] += o.z; ls[g][3] += o.w;
            ls2[g][0] += o.x * o.x; ls2[g][1] += o.y * o.y;
            ls2[g][2] += o.z * o.z; ls2[g][3] += o.w * o.w;
            *(float4*)(out + row * 256 + n) = o;
        }
    }

    // ---- BN partials: per-column reduce over the CTA's 128 rows (two smem passes) ----
    float* red = &As[0][0];            // 2048 floats == 256 threads * 8 slots
    __syncthreads();
#pragma unroll
    for (int g = 0; g < 2; g++)
#pragma unroll
        for (int i = 0; i < 4; i++) red[tid * 8 + g * 4 + i] = ls[g][i];
    __syncthreads();
    float sv = 0.f;
    if (tid < 128) {
        int g = tid >> 6, txr = (tid >> 2) & 15, ir = tid & 3;
#pragma unroll
        for (int k = 0; k < 16; k++) sv += red[(k * 16 + txr) * 8 + g * 4 + ir];
    }
    __syncthreads();
#pragma unroll
    for (int g = 0; g < 2; g++)
#pragma unroll
        for (int i = 0; i < 4; i++) red[tid * 8 + g * 4 + i] = ls2[g][i];
    __syncthreads();
    if (tid < 128) {
        int g = tid >> 6, txr = (tid >> 2) & 15, ir = tid & 3;
        float s2 = 0.f;
#pragma unroll
        for (int k = 0; k < 16; k++) s2 += red[(k * 16 + txr) * 8 + g * 4 + ir];
        int col = n0 + g * 64 + txr * 4 + ir;
        g_part[blockIdx.x * 512 + col] = sv;
        g_part[blockIdx.x * 512 + 256 + col] = s2;
    }
}

// ================= mean pool + head =================
__global__ void __launch_bounds__(256) pool1() {
    int b = blockIdx.x >> 3;
    int c = blockIdx.x & 7;
    int e = threadIdx.x;
    const float* p = g_x + ((size_t)b * TLEN + c * 256) * EF + e;
    float s = 0.f;
#pragma unroll 8
    for (int t = 0; t < 256; t++) s += p[(size_t)t * EF];
    g_poolpart[(b * 8 + c) * EF + e] = s;
}

__global__ void __launch_bounds__(256) pool2() {
    int b = blockIdx.x;
    int e = threadIdx.x;
    float s = 0.f;
    for (int c = 0; c < 8; c++) s += g_poolpart[(b * 8 + c) * EF + e];
    g_pool[b * EF + e] = s * (1.0f / (float)TLEN);
}

__global__ void head(const float* __restrict__ Wout, const float* __restrict__ bout,
                     float* __restrict__ out) {
    int tid = threadIdx.x;
    if (tid >= 320) return;
    int b = tid / 10;
    int o = tid % 10;
    float s = bout[o];
    const float* p = g_pool + b * EF;
    for (int e = 0; e < 256; e++) s = fmaf(p[e], Wout[e * 10 + o], s);
    out[b * 10 + o] = s;
}

// ================= host orchestration =================
extern "C" void kernel_launch(void* const* d_in, const int* in_sizes, int n_in,
                              void* d_out, int out_size) {
    const float* x    = (const float*)d_in[0];   // [32,2048,64]
    const float* Wenc = (const float*)d_in[1];   // [64,256]
    const float* benc = (const float*)d_in[2];   // [256]
    const float* nul  = (const float*)d_in[3];   // [6,256]
    const float* thl  = (const float*)d_in[4];   // [6,256]
    const float* Bre  = (const float*)d_in[5];   // [6,256,256]
    const float* Bim  = (const float*)d_in[6];
    const float* Cre  = (const float*)d_in[7];   // [6,256,256]
    const float* Cim  = (const float*)d_in[8];
    const float* Dd   = (const float*)d_in[9];   // [6,256]
    const float* W1   = (const float*)d_in[10];  // [6,256,1024]
    const float* b1   = (const float*)d_in[11];  // [6,1024]
    const float* W2   = (const float*)d_in[12];  // [6,512,256]
    const float* b2   = (const float*)d_in[13];  // [6,256]
    const float* bns  = (const float*)d_in[14];  // [6,256]
    const float* bnb  = (const float*)d_in[15];  // [6,256]
    const float* Wout = (const float*)d_in[16];  // [256,10]
    const float* bout = (const float*)d_in[17];  // [10]

    dim3 g2(512, 2), g4(512, 4), g8(512, 8);

    // encoder: y = x @ W_enc + b_enc   (writes g_y + BN partials)
    gemm_nn<0><<<g2, 256>>>(x, 64, Wenc, benc);

    int xsel = 0;  // 0 = read g_y, 1 = read g_x
    for (int i = 0; i < NBLK; i++) {
        bn_stage2<<<1, 256>>>(bns + i * 256, bnb + i * 256);
        lam_kernel<<<1, 256>>>(nul + i * 256, thl + i * 256);
        gemm_bu2<<<g4, 256>>>(xsel, Bre + (size_t)i * 65536, Bim + (size_t)i * 65536);
        scan_carry<<<BB * NC, 256>>>();
        scan_prefix<<<BB, 256>>>();
        scan_final<<<BB * NC, 256>>>();
        gemm_cproj<<<g2, 256>>>(Cre + (size_t)i * 65536, Cim + (size_t)i * 65536,
                                Dd + i * 256, xsel);
        gemm_glu<<<g8, 256>>>(W1 + (size_t)i * 256 * 1024, b1 + i * 1024);
        gemm_nn<1><<<g2, 256>>>(nullptr, 512, W2 + (size_t)i * 512 * 256, b2 + i * 256);
        xsel = 1;
    }
    pool1<<<BB * 8, 256>>>();
    pool2<<<BB, 256>>>();
    head<<<1, 320>>>(Wout, bout, (float*)d_out);
}

// round 10
// speedup vs baseline: 1.4834x; 1.0004x over previous
#include <cuda_runtime.h>

// ---------------- problem constants ----------------
#define MTOT 65536      // B*T tokens
#define EF   256        // E features
#define HF   256        // H state size
#define LF   1024       // MLP hidden (pre-GLU)
#define NBLK 6
#define TLEN 2048
#define BB   32
#define NC   16         // scan chunks (of 128)
#define TC   128        // chunk length (NC*TC == TLEN)

// ---------------- scratch (device globals; no allocation allowed) ----------------
static __device__ float g_y[(size_t)MTOT * EF];      // encoder output / residual anchor
static __device__ float g_x[(size_t)MTOT * EF];      // current block output
static __device__ float g_bure[(size_t)MTOT * HF];
static __device__ float g_buim[(size_t)MTOT * HF];
static __device__ float g_hre[(size_t)MTOT * HF];
static __device__ float g_him[(size_t)MTOT * HF];
static __device__ float g_u[(size_t)MTOT * EF];
static __device__ float g_g[(size_t)MTOT * (LF / 2)];
static __device__ float g_part[512 * 512];           // BN/pool partials: [512 m-blocks][256 sum | 256 sumsq]
static __device__ float g_bna[EF];                   // BN fold: a = rsqrt(var+eps)*scale
static __device__ float g_bnc[EF];                   // BN fold: c = bias - mu*a
static __device__ float g_lr[HF], g_li[HF], g_gam[HF];
static __device__ float g_l8r[HF], g_l8i[HF];        // lam^8
static __device__ float g_L128r[HF], g_L128i[HF];    // lam^128
static __device__ float g_car_re[BB * NC * HF], g_car_im[BB * NC * HF];
static __device__ float g_pre_re[BB * NC * HF], g_pre_im[BB * NC * HF];

// ================= BN finalize (partials produced by GEMM epilogues) =================
__global__ void __launch_bounds__(256) bn_stage2(const float* __restrict__ scale,
                                                 const float* __restrict__ bias) {
    int e = threadIdx.x;
    float s = 0.f, s2 = 0.f;
    for (int p = 0; p < 512; p++) {
        s += g_part[p * 512 + e];
        s2 += g_part[p * 512 + 256 + e];
    }
    const float inv = 1.0f / 65536.0f;
    float mu = s * inv;
    float var = fmaxf(s2 * inv - mu * mu, 0.0f);
    float a = rsqrtf(var + 1e-5f) * scale[e];
    g_bna[e] = a;
    g_bnc[e] = bias[e] - mu * a;
}

// ================= lambda / gamma precompute =================
__global__ void lam_kernel(const float* __restrict__ nul, const float* __restrict__ thl) {
    int h = threadIdx.x;
    float nu = expf(nul[h]);
    float th = expf(thl[h]);
    float r = expf(-nu);
    float sn, cs;
    sincosf(th, &sn, &cs);
    float lr = r * cs, li = r * sn;
    g_lr[h] = lr;
    g_li[h] = li;
    g_gam[h] = sqrtf(fmaxf(1.0f - r * r, 1e-12f));
    float ar = lr, ai = li;
#pragma unroll
    for (int s = 0; s < 3; s++) {        // lam^8
        float nr = ar * ar - ai * ai;
        float ni = 2.0f * ar * ai;
        ar = nr;
        ai = ni;
    }
    g_l8r[h] = ar;
    g_l8i[h] = ai;
#pragma unroll
    for (int s = 0; s < 4; s++) {        // lam^128
        float nr = ar * ar - ai * ai;
        float ni = 2.0f * ar * ai;
        ar = nr;
        ai = ni;
    }
    g_L128r[h] = ar;
    g_L128i[h] = ai;
}

// ================= GEMM: (bure,buim) = BN(x) @ [Bre^T, Bim^T] * gamma  (fused dual-B TN)
//   + epilogue computes per-chunk scan carries (chunk = this CTA's 128 rows) =============
__global__ void __launch_bounds__(256) gemm_bu2(int xsel, const float* __restrict__ Wr,
                                                const float* __restrict__ Wi) {
    const float* A = xsel ? g_x : g_y;
    __shared__ __align__(16) float As[16][128];
    __shared__ __align__(16) float Bsr[16][64];
    __shared__ __align__(16) float Bsi[16][64];
    const int tid = threadIdx.x;
    const int m0 = blockIdx.x * 128;
    const int n0 = blockIdx.y * 64;
    const int tx = tid & 15;
    const int ty = tid >> 4;
    const int lr = tid >> 2;
    const int lk = (tid & 3) * 4;
    float accr[8][4], acci[8][4];
#pragma unroll
    for (int j = 0; j < 8; j++)
#pragma unroll
        for (int i = 0; i < 4; i++) { accr[j][i] = 0.f; acci[j][i] = 0.f; }

    for (int k0 = 0; k0 < 256; k0 += 16) {
        float4 a0 = *(const float4*)(A + (size_t)(m0 + lr) * 256 + k0 + lk);
        float4 a1 = *(const float4*)(A + (size_t)(m0 + lr + 64) * 256 + k0 + lk);
        float4 wr = *(const float4*)(Wr + (size_t)(n0 + lr) * 256 + k0 + lk);
        float4 wi = *(const float4*)(Wi + (size_t)(n0 + lr) * 256 + k0 + lk);
        float4 ba = *(const float4*)(g_bna + k0 + lk);
        float4 bc = *(const float4*)(g_bnc + k0 + lk);
        a0.x = fmaf(ba.x, a0.x, bc.x); a0.y = fmaf(ba.y, a0.y, bc.y);
        a0.z = fmaf(ba.z, a0.z, bc.z); a0.w = fmaf(ba.w, a0.w, bc.w);
        a1.x = fmaf(ba.x, a1.x, bc.x); a1.y = fmaf(ba.y, a1.y, bc.y);
        a1.z = fmaf(ba.z, a1.z, bc.z); a1.w = fmaf(ba.w, a1.w, bc.w);
        __syncthreads();
        As[lk + 0][lr] = a0.x; As[lk + 1][lr] = a0.y; As[lk + 2][lr] = a0.z; As[lk + 3][lr] = a0.w;
        As[lk + 0][lr + 64] = a1.x; As[lk + 1][lr + 64] = a1.y;
        As[lk + 2][lr + 64] = a1.z; As[lk + 3][lr + 64] = a1.w;
        Bsr[lk + 0][lr] = wr.x; Bsr[lk + 1][lr] = wr.y; Bsr[lk + 2][lr] = wr.z; Bsr[lk + 3][lr] = wr.w;
        Bsi[lk + 0][lr] = wi.x; Bsi[lk + 1][lr] = wi.y; Bsi[lk + 2][lr] = wi.z; Bsi[lk + 3][lr] = wi.w;
        __syncthreads();
#pragma unroll
        for (int kk = 0; kk < 16; kk++) {
            float4 av0 = *(const float4*)&As[kk][ty * 8];
            float4 av1 = *(const float4*)&As[kk][ty * 8 + 4];
            float4 br = *(const float4*)&Bsr[kk][tx * 4];
            float4 bi = *(const float4*)&Bsi[kk][tx * 4];
            float a[8] = {av0.x, av0.y, av0.z, av0.w, av1.x, av1.y, av1.z, av1.w};
            float brv[4] = {br.x, br.y, br.z, br.w};
            float biv[4] = {bi.x, bi.y, bi.z, bi.w};
#pragma unroll
            for (int j = 0; j < 8; j++)
#pragma unroll
                for (int i = 0; i < 4; i++) {
                    accr[j][i] = fmaf(a[j], brv[i], accr[j][i]);
                    acci[j][i] = fmaf(a[j], biv[i], acci[j][i]);
                }
        }
    }
    float4 gm = *(const float4*)(g_gam + n0 + tx * 4);
    // local 8-step scan state per column (complex)
    float sr[4] = {0.f, 0.f, 0.f, 0.f}, si[4] = {0.f, 0.f, 0.f, 0.f};
    float lrv[4], liv[4];
#pragma unroll
    for (int i = 0; i < 4; i++) {
        lrv[i] = g_lr[n0 + tx * 4 + i];
        liv[i] = g_li[n0 + tx * 4 + i];
    }
#pragma unroll
    for (int j = 0; j < 8; j++) {
        size_t row = (size_t)(m0 + ty * 8 + j);
        float ur[4], ui[4];
        ur[0] = accr[j][0] * gm.x; ur[1] = accr[j][1] * gm.y;
        ur[2] = accr[j][2] * gm.z; ur[3] = accr[j][3] * gm.w;
        ui[0] = acci[j][0] * gm.x; ui[1] = acci[j][1] * gm.y;
        ui[2] = acci[j][2] * gm.z; ui[3] = acci[j][3] * gm.w;
        *(float4*)(g_bure + row * 256 + n0 + tx * 4) = make_float4(ur[0], ur[1], ur[2], ur[3]);
        *(float4*)(g_buim + row * 256 + n0 + tx * 4) = make_float4(ui[0], ui[1], ui[2], ui[3]);
#pragma unroll
        for (int i = 0; i < 4; i++) {
            float nr = fmaf(lrv[i], sr[i], fmaf(-liv[i], si[i], ur[i]));
            float ni = fmaf(lrv[i], si[i], fmaf(liv[i], sr[i], ui[i]));
            sr[i] = nr;
            si[i] = ni;
        }
    }
    // combine 16 ty-groups (each covers 8 rows) with lam^8 -> chunk carry
    __syncthreads();
#pragma unroll
    for (int i = 0; i < 4; i++) {
        As[ty][tx * 4 + i] = sr[i];
        As[ty][64 + tx * 4 + i] = si[i];
    }
    __syncthreads();
    if (tid < 64) {
        int col = tid;
        int n = n0 + col;
        float l8r = g_l8r[n], l8i = g_l8i[n];
        float Hr = 0.f, Hi = 0.f;
#pragma unroll
        for (int gI = 0; gI < 16; gI++) {
            float ur = As[gI][col], ui = As[gI][64 + col];
            float nr = fmaf(l8r, Hr, fmaf(-l8i, Hi, ur));
            float ni = fmaf(l8r, Hi, fmaf(l8i, Hr, ui));
            Hr = nr;
            Hi = ni;
        }
        int b = m0 >> 11;               // batch
        int cch = (m0 >> 7) & 15;       // chunk within batch
        int ci = (b * NC + cch) * HF + n;
        g_car_re[ci] = Hr;
        g_car_im[ci] = Hi;
    }
}

// ================= scan: prefix combine (lam^128) + final re-sweep =================
__global__ void __launch_bounds__(256) scan_prefix() {
    int h = threadIdx.x;
    int b = blockIdx.x;
    float Lr = g_L128r[h], Li = g_L128i[h];
    float Hr = 0.f, Hi = 0.f;
    for (int c = 0; c < NC; c++) {
        int ci = (b * NC + c) * HF + h;
        g_pre_re[ci] = Hr;
        g_pre_im[ci] = Hi;
        float cr = g_car_re[ci], cim = g_car_im[ci];
        float nr = fmaf(Lr, Hr, fmaf(-Li, Hi, cr));
        float ni = fmaf(Lr, Hi, fmaf(Li, Hr, cim));
        Hr = nr;
        Hi = ni;
    }
}

__global__ void __launch_bounds__(256) scan_final() {
    int h = threadIdx.x;
    int c = blockIdx.x & 15;
    int b = blockIdx.x >> 4;
    float lr = g_lr[h], li = g_li[h];
    int ci = (b * NC + c) * HF + h;
    float hr = g_pre_re[ci], hi = g_pre_im[ci];
    size_t base = ((size_t)b * TLEN + c * TC) * HF + h;
#pragma unroll 4
    for (int t = 0; t < TC; t++) {
        size_t idx = base + (size_t)t * HF;
        float ur = g_bure[idx];
        float ui = g_buim[idx];
        float nr = fmaf(lr, hr, fmaf(-li, hi, ur));
        float ni = fmaf(lr, hi, fmaf(li, hr, ui));
        hr = nr;
        hi = ni;
        g_hre[idx] = hr;
        g_him[idx] = hi;
    }
}

// ================= GEMM: u = Re(hs @ Cc) + D*BN(x)  (dual TN, wide N=128) =================
__global__ void __launch_bounds__(256) gemm_cproj(const float* __restrict__ Wr,
                                                  const float* __restrict__ Wi,
                                                  const float* __restrict__ Dv, int xsel) {
    const float* Xin = xsel ? g_x : g_y;
    __shared__ __align__(16) float Asr[16][128];
    __shared__ __align__(16) float Asi[16][128];
    __shared__ __align__(16) float Bsr[16][128];
    __shared__ __align__(16) float Bsi[16][128];
    const int tid = threadIdx.x;
    const int m0 = blockIdx.x * 128;
    const int n0 = blockIdx.y * 128;
    const int tx = tid & 15;
    const int ty = tid >> 4;
    const int lr = tid >> 2;
    const int lk = (tid & 3) * 4;
    float acc[8][2][4];
#pragma unroll
    for (int j = 0; j < 8; j++)
#pragma unroll
        for (int g = 0; g < 2; g++)
#pragma unroll
            for (int i = 0; i < 4; i++) acc[j][g][i] = 0.f;

    for (int k0 = 0; k0 < 256; k0 += 16) {
        float4 ar0 = *(const float4*)(g_hre + (size_t)(m0 + lr) * 256 + k0 + lk);
        float4 ar1 = *(const float4*)(g_hre + (size_t)(m0 + lr + 64) * 256 + k0 + lk);
        float4 ai0 = *(const float4*)(g_him + (size_t)(m0 + lr) * 256 + k0 + lk);
        float4 ai1 = *(const float4*)(g_him + (size_t)(m0 + lr + 64) * 256 + k0 + lk);
        float4 wr0 = *(const float4*)(Wr + (size_t)(n0 + lr) * 256 + k0 + lk);
        float4 wr1 = *(const float4*)(Wr + (size_t)(n0 + lr + 64) * 256 + k0 + lk);
        float4 wi0 = *(const float4*)(Wi + (size_t)(n0 + lr) * 256 + k0 + lk);
        float4 wi1 = *(const float4*)(Wi + (size_t)(n0 + lr + 64) * 256 + k0 + lk);
        __syncthreads();
        Asr[lk + 0][lr] = ar0.x; Asr[lk + 1][lr] = ar0.y; Asr[lk + 2][lr] = ar0.z; Asr[lk + 3][lr] = ar0.w;
        Asr[lk + 0][lr + 64] = ar1.x; Asr[lk + 1][lr + 64] = ar1.y;
        Asr[lk + 2][lr + 64] = ar1.z; Asr[lk + 3][lr + 64] = ar1.w;
        Asi[lk + 0][lr] = ai0.x; Asi[lk + 1][lr] = ai0.y; Asi[lk + 2][lr] = ai0.z; Asi[lk + 3][lr] = ai0.w;
        Asi[lk + 0][lr + 64] = ai1.x; Asi[lk + 1][lr + 64] = ai1.y;
        Asi[lk + 2][lr + 64] = ai1.z; Asi[lk + 3][lr + 64] = ai1.w;
        Bsr[lk + 0][lr] = wr0.x; Bsr[lk + 1][lr] = wr0.y; Bsr[lk + 2][lr] = wr0.z; Bsr[lk + 3][lr] = wr0.w;
        Bsr[lk + 0][lr + 64] = wr1.x; Bsr[lk + 1][lr + 64] = wr1.y;
        Bsr[lk + 2][lr + 64] = wr1.z; Bsr[lk + 3][lr + 64] = wr1.w;
        Bsi[lk + 0][lr] = wi0.x; Bsi[lk + 1][lr] = wi0.y; Bsi[lk + 2][lr] = wi0.z; Bsi[lk + 3][lr] = wi0.w;
        Bsi[lk + 0][lr + 64] = wi1.x; Bsi[lk + 1][lr + 64] = wi1.y;
        Bsi[lk + 2][lr + 64] = wi1.z; Bsi[lk + 3][lr + 64] = wi1.w;
        __syncthreads();
#pragma unroll
        for (int kk = 0; kk < 16; kk++) {
            float4 r0 = *(const float4*)&Asr[kk][ty * 8];
            float4 r1 = *(const float4*)&Asr[kk][ty * 8 + 4];
            float4 i0 = *(const float4*)&Asi[kk][ty * 8];
            float4 i1 = *(const float4*)&Asi[kk][ty * 8 + 4];
            float4 br0 = *(const float4*)&Bsr[kk][tx * 4];
            float4 br1 = *(const float4*)&Bsr[kk][tx * 4 + 64];
            float4 bi0 = *(const float4*)&Bsi[kk][tx * 4];
            float4 bi1 = *(const float4*)&Bsi[kk][tx * 4 + 64];
            float arv[8] = {r0.x, r0.y, r0.z, r0.w, r1.x, r1.y, r1.z, r1.w};
            float aiv[8] = {i0.x, i0.y, i0.z, i0.w, i1.x, i1.y, i1.z, i1.w};
            float brv[2][4] = {{br0.x, br0.y, br0.z, br0.w}, {br1.x, br1.y, br1.z, br1.w}};
            float biv[2][4] = {{bi0.x, bi0.y, bi0.z, bi0.w}, {bi1.x, bi1.y, bi1.z, bi1.w}};
#pragma unroll
            for (int j = 0; j < 8; j++)
#pragma unroll
                for (int g = 0; g < 2; g++)
#pragma unroll
                    for (int i = 0; i < 4; i++) {
                        acc[j][g][i] = fmaf(arv[j], brv[g][i], acc[j][g][i]);
                        acc[j][g][i] = fmaf(-aiv[j], biv[g][i], acc[j][g][i]);
                    }
        }
    }
#pragma unroll
    for (int g = 0; g < 2; g++) {
        int n = n0 + g * 64 + tx * 4;
        float4 dq = *(const float4*)(Dv + n);
        float4 ba = *(const float4*)(g_bna + n);
        float4 bc = *(const float4*)(g_bnc + n);
#pragma unroll
        for (int j = 0; j < 8; j++) {
            size_t row = (size_t)(m0 + ty * 8 + j);
            float4 xv = *(const float4*)(Xin + row * 256 + n);
            float4 o;
            o.x = acc[j][g][0] + dq.x * fmaf(ba.x, xv.x, bc.x);
            o.y = acc[j][g][1] + dq.y * fmaf(ba.y, xv.y, bc.y);
            o.z = acc[j][g][2] + dq.z * fmaf(ba.z, xv.z, bc.z);
            o.w = acc[j][g][3] + dq.w * fmaf(ba.w, xv.w, bc.w);
            *(float4*)(g_u + row * 256 + n) = o;
        }
    }
}

// ================= GEMM: g = GLU(u @ W1 + b1)   (NN, dual-B tile) =================
__global__ void __launch_bounds__(256) gemm_glu(const float* __restrict__ W1,
                                                const float* __restrict__ b1) {
    __shared__ __align__(16) float As[16][128];
    __shared__ __align__(16) float Ba[16][64];
    __shared__ __align__(16) float Bb[16][64];
    const int tid = threadIdx.x;
    const int m0 = blockIdx.x * 128;
    const int n0 = blockIdx.y * 64;  // 0..448 (within 512)
    const int tx = tid & 15;
    const int ty = tid >> 4;
    const int lr = tid >> 2;
    const int lk = (tid & 3) * 4;
    const int bk = tid >> 4;
    const int bn = (tid & 15) * 4;
    float acca[8][4], accb[8][4];
#pragma unroll
    for (int j = 0; j < 8; j++)
#pragma unroll
        for (int i = 0; i < 4; i++) { acca[j][i] = 0.f; accb[j][i] = 0.f; }

    for (int k0 = 0; k0 < 256; k0 += 16) {
        float4 a0 = *(const float4*)(g_u + (size_t)(m0 + lr) * 256 + k0 + lk);
        float4 a1 = *(const float4*)(g_u + (size_t)(m0 + lr + 64) * 256 + k0 + lk);
        float4 wa = *(const float4*)(W1 + (size_t)(k0 + bk) * 1024 + n0 + bn);
        float4 wb = *(const float4*)(W1 + (size_t)(k0 + bk) * 1024 + 512 + n0 + bn);
        __syncthreads();
        As[lk + 0][lr] = a0.x; As[lk + 1][lr] = a0.y; As[lk + 2][lr] = a0.z; As[lk + 3][lr] = a0.w;
        As[lk + 0][lr + 64] = a1.x; As[lk + 1][lr + 64] = a1.y;
        As[lk + 2][lr + 64] = a1.z; As[lk + 3][lr + 64] = a1.w;
        *(float4*)&Ba[bk][bn] = wa;
        *(float4*)&Bb[bk][bn] = wb;
        __syncthreads();
#pragma unroll
        for (int kk = 0; kk < 16; kk++) {
            float4 av0 = *(const float4*)&As[kk][ty * 8];
            float4 av1 = *(const float4*)&As[kk][ty * 8 + 4];
            float4 bva = *(const float4*)&Ba[kk][tx * 4];
            float4 bvb = *(const float4*)&Bb[kk][tx * 4];
            float a[8] = {av0.x, av0.y, av0.z, av0.w, av1.x, av1.y, av1.z, av1.w};
            float ba_[4] = {bva.x, bva.y, bva.z, bva.w};
            float bb_[4] = {bvb.x, bvb.y, bvb.z, bvb.w};
#pragma unroll
            for (int j = 0; j < 8; j++)
#pragma unroll
                for (int i = 0; i < 4; i++) {
                    acca[j][i] = fmaf(a[j], ba_[i], acca[j][i]);
                    accb[j][i] = fmaf(a[j], bb_[i], accb[j][i]);
                }
        }
    }
    float4 b1a = *(const float4*)(b1 + n0 + tx * 4);
    float4 b1b = *(const float4*)(b1 + 512 + n0 + tx * 4);
#pragma unroll
    for (int j = 0; j < 8; j++) {
        float za[4], zb[4];
        za[0] = acca[j][0] + b1a.x; za[1] = acca[j][1] + b1a.y;
        za[2] = acca[j][2] + b1a.z; za[3] = acca[j][3] + b1a.w;
        zb[0] = accb[j][0] + b1b.x; zb[1] = accb[j][1] + b1b.y;
        zb[2] = accb[j][2] + b1b.z; zb[3] = accb[j][3] + b1b.w;
        float4 o;
        o.x = __fdividef(za[0], 1.0f + __expf(-zb[0]));
        o.y = __fdividef(za[1], 1.0f + __expf(-zb[1]));
        o.z = __fdividef(za[2], 1.0f + __expf(-zb[2]));
        o.w = __fdividef(za[3], 1.0f + __expf(-zb[3]));
        *(float4*)(g_g + (size_t)(m0 + ty * 8 + j) * 512 + n0 + tx * 4) = o;
    }
}

// ================= GEMM NN wide (encoder ROLE=0, MLP2+residual ROLE=1; N-tile 128) =======
template <int ROLE>
__global__ void __launch_bounds__(256) gemm_nn(const float* __restrict__ Aext, int K,
                                               const float* __restrict__ B,
                                               const float* __restrict__ bias) {
    const float* A = (ROLE == 0) ? Aext : g_g;
    float* out = (ROLE == 0) ? g_y : g_x;
    __shared__ __align__(16) float As[16][128];
    __shared__ __align__(16) float Bs[16][128];
    const int tid = threadIdx.x;
    const int m0 = blockIdx.x * 128;
    const int n0 = blockIdx.y * 128;
    const int tx = tid & 15;
    const int ty = tid >> 4;
    const int lr = tid >> 2;
    const int lk = (tid & 3) * 4;
    const int bk = tid >> 4;
    const int bn = (tid & 15) * 4;
    float acc[8][2][4];
#pragma unroll
    for (int j = 0; j < 8; j++)
#pragma unroll
        for (int g = 0; g < 2; g++)
#pragma unroll
            for (int i = 0; i < 4; i++) acc[j][g][i] = 0.f;

    for (int k0 = 0; k0 < K; k0 += 16) {
        float4 a0 = *(const float4*)(A + (size_t)(m0 + lr) * K + k0 + lk);
        float4 a1 = *(const float4*)(A + (size_t)(m0 + lr + 64) * K + k0 + lk);
        float4 wv0 = *(const float4*)(B + (size_t)(k0 + bk) * 256 + n0 + bn);
        float4 wv1 = *(const float4*)(B + (size_t)(k0 + bk) * 256 + n0 + 64 + bn);
        __syncthreads();
        As[lk + 0][lr] = a0.x; As[lk + 1][lr] = a0.y; As[lk + 2][lr] = a0.z; As[lk + 3][lr] = a0.w;
        As[lk + 0][lr + 64] = a1.x; As[lk + 1][lr + 64] = a1.y;
        As[lk + 2][lr + 64] = a1.z; As[lk + 3][lr + 64] = a1.w;
        *(float4*)&Bs[bk][bn] = wv0;
        *(float4*)&Bs[bk][bn + 64] = wv1;
        __syncthreads();
#pragma unroll
        for (int kk = 0; kk < 16; kk++) {
            float4 av0 = *(const float4*)&As[kk][ty * 8];
            float4 av1 = *(const float4*)&As[kk][ty * 8 + 4];
            float4 bv0 = *(const float4*)&Bs[kk][tx * 4];
            float4 bv1 = *(const float4*)&Bs[kk][tx * 4 + 64];
            float a[8] = {av0.x, av0.y, av0.z, av0.w, av1.x, av1.y, av1.z, av1.w};
            float bv[2][4] = {{bv0.x, bv0.y, bv0.z, bv0.w}, {bv1.x, bv1.y, bv1.z, bv1.w}};
#pragma unroll
            for (int j = 0; j < 8; j++)
#pragma unroll
                for (int g = 0; g < 2; g++)
#pragma unroll
                    for (int i = 0; i < 4; i++)
                        acc[j][g][i] = fmaf(a[j], bv[g][i], acc[j][g][i]);
        }
    }

    float ls[2][4], ls2[2][4];
#pragma unroll
    for (int g = 0; g < 2; g++)
#pragma unroll
        for (int i = 0; i < 4; i++) { ls[g][i] = 0.f; ls2[g][i] = 0.f; }
#pragma unroll
    for (int g = 0; g < 2; g++) {
        int n = n0 + g * 64 + tx * 4;
        float4 bq = *(const float4*)(bias + n);
#pragma unroll
        for (int j = 0; j < 8; j++) {
            size_t row = (size_t)(m0 + ty * 8 + j);
            float4 o;
            o.x = acc[j][g][0] + bq.x; o.y = acc[j][g][1] + bq.y;
            o.z = acc[j][g][2] + bq.z; o.w = acc[j][g][3] + bq.w;
            if (ROLE == 1) {
                float4 yv = *(const float4*)(g_y + row * 256 + n);
                o.x += yv.x; o.y += yv.y; o.z += yv.z; o.w += yv.w;
            }
            ls[g][0] += o.x; ls[g][1] += o.y; ls[g][2] += o.z; ls[g][3] += o.w;
            ls2[g][0] += o.x * o.x; ls2[g][1] += o.y * o.y;
            ls2[g][2] += o.z * o.z; ls2[g][3] += o.w * o.w;
            *(float4*)(out + row * 256 + n) = o;
        }
    }

    // ---- BN/pool partials: per-column reduce over the CTA's 128 rows ----
    float* red = &As[0][0];            // 2048 floats == 256 threads * 8 slots
    __syncthreads();
#pragma unroll
    for (int g = 0; g < 2; g++)
#pragma unroll
        for (int i = 0; i < 4; i++) red[tid * 8 + g * 4 + i] = ls[g][i];
    __syncthreads();
    float sv = 0.f;
    if (tid < 128) {
        int g = tid >> 6, txr = (tid >> 2) & 15, ir = tid & 3;
#pragma unroll
        for (int k = 0; k < 16; k++) sv += red[(k * 16 + txr) * 8 + g * 4 + ir];
    }
    __syncthreads();
#pragma unroll
    for (int g = 0; g < 2; g++)
#pragma unroll
        for (int i = 0; i < 4; i++) red[tid * 8 + g * 4 + i] = ls2[g][i];
    __syncthreads();
    if (tid < 128) {
        int g = tid >> 6, txr = (tid >> 2) & 15, ir = tid & 3;
        float s2 = 0.f;
#pragma unroll
        for (int k = 0; k < 16; k++) s2 += red[(k * 16 + txr) * 8 + g * 4 + ir];
        int col = n0 + g * 64 + txr * 4 + ir;
        g_part[blockIdx.x * 512 + col] = sv;
        g_part[blockIdx.x * 512 + 256 + col] = s2;
    }
}

// ================= fused mean-pool + head (reads g_part of last block output) =========
__global__ void __launch_bounds__(256) pool_head(const float* __restrict__ Wout,
                                                 const float* __restrict__ bout,
                                                 float* __restrict__ out) {
    __shared__ float pooled[256];
    int b = blockIdx.x;
    int e = threadIdx.x;
    float s = 0.f;
#pragma unroll
    for (int k = 0; k < 16; k++) s += g_part[(b * 16 + k) * 512 + e];
    pooled[e] = s * (1.0f / (float)TLEN);
    __syncthreads();
    if (e < 10) {
        float acc = bout[e];
        for (int q = 0; q < 256; q++) acc = fmaf(pooled[q], Wout[q * 10 + e], acc);
        out[b * 10 + e] = acc;
    }
}

// ================= host orchestration =================
extern "C" void kernel_launch(void* const* d_in, const int* in_sizes, int n_in,
                              void* d_out, int out_size) {
    const float* x    = (const float*)d_in[0];   // [32,2048,64]
    const float* Wenc = (const float*)d_in[1];   // [64,256]
    const float* benc = (const float*)d_in[2];   // [256]
    const float* nul  = (const float*)d_in[3];   // [6,256]
    const float* thl  = (const float*)d_in[4];   // [6,256]
    const float* Bre  = (const float*)d_in[5];   // [6,256,256]
    const float* Bim  = (const float*)d_in[6];
    const float* Cre  = (const float*)d_in[7];   // [6,256,256]
    const float* Cim  = (const float*)d_in[8];
    const float* Dd   = (const float*)d_in[9];   // [6,256]
    const float* W1   = (const float*)d_in[10];  // [6,256,1024]
    const float* b1   = (const float*)d_in[11];  // [6,1024]
    const float* W2   = (const float*)d_in[12];  // [6,512,256]
    const float* b2   = (const float*)d_in[13];  // [6,256]
    const float* bns  = (const float*)d_in[14];  // [6,256]
    const float* bnb  = (const float*)d_in[15];  // [6,256]
    const float* Wout = (const float*)d_in[16];  // [256,10]
    const float* bout = (const float*)d_in[17];  // [10]

    dim3 g2(512, 2), g4(512, 4), g8(512, 8);

    // encoder: y = x @ W_enc + b_enc   (writes g_y + BN partials)
    gemm_nn<0><<<g2, 256>>>(x, 64, Wenc, benc);

    int xsel = 0;  // 0 = read g_y, 1 = read g_x
    for (int i = 0; i < NBLK; i++) {
        bn_stage2<<<1, 256>>>(bns + i * 256, bnb + i * 256);
        lam_kernel<<<1, 256>>>(nul + i * 256, thl + i * 256);
        gemm_bu2<<<g4, 256>>>(xsel, Bre + (size_t)i * 65536, Bim + (size_t)i * 65536);
        scan_prefix<<<BB, 256>>>();
        scan_final<<<BB * NC, 256>>>();
        gemm_cproj<<<g2, 256>>>(Cre + (size_t)i * 65536, Cim + (size_t)i * 65536,
                                Dd + i * 256, xsel);
        gemm_glu<<<g8, 256>>>(W1 + (size_t)i * 256 * 1024, b1 + i * 1024);
        gemm_nn<1><<<g2, 256>>>(nullptr, 512, W2 + (size_t)i * 512 * 256, b2 + i * 256);
        xsel = 1;
    }
    pool_head<<<BB, 256>>>(Wout, bout, (float*)d_out);
}